// round 14
// baseline (speedup 1.0000x reference)
#include <cuda_runtime.h>
#include <cuda_fp16.h>
#include <math.h>
#include <stdint.h>

// ---------------- problem constants ----------------
#define BB   2
#define DIM  256
#define NH   8
#define HD   32
#define NL   4
#define NP   4
#define HID  1024
#define NQ   5440
#define MROWS (BB*NQ)   // 10880 = 85*128

__device__ __constant__ int LVL_SIZE[4]  = {64, 32, 16, 8};
__device__ __constant__ int LVL_START[4] = {0, 4096, 5120, 5376};

// ---------------- scratch ----------------
__device__ __half g_qh   [(size_t)MROWS * DIM];
__device__ float  g_q32  [(size_t)MROWS * DIM];
__device__ float  g_value[(size_t)MROWS * DIM];
__device__ __half g_vnh  [(size_t)MROWS * DIM];
__device__ __half g_valh [(size_t)MROWS * DIM];     // val in HALF (deform input)
__device__ float  g_offaw[(size_t)MROWS * 384];
__device__ __half g_samph[(size_t)MROWS * DIM];
__device__ float  g_x    [(size_t)MROWS * DIM];
__device__ __half g_xh   [(size_t)MROWS * DIM];
__device__ __half g_h1h  [(size_t)MROWS * HID];     // h1 in HALF (dwconv input)
__device__ __half g_h2h  [(size_t)MROWS * HID];
// transposed weights [N, K] in half
__device__ __half g_WT_val  [DIM * DIM];
__device__ __half g_WT_offaw[384 * DIM];
__device__ float  g_b_offaw [384];
__device__ __half g_WT_out  [DIM * DIM];
__device__ __half g_WT_fc1  [HID * DIM];
__device__ __half g_WT_fc2  [DIM * HID];

// ---------------- cp.async helpers ----------------
__device__ __forceinline__ void cp_async16(uint32_t smem, const void* gmem) {
    asm volatile("cp.async.cg.shared.global [%0], [%1], 16;" :: "r"(smem), "l"(gmem));
}
#define CP_COMMIT() asm volatile("cp.async.commit_group;")
#define CP_WAIT0()  asm volatile("cp.async.wait_group 0;")
#define CP_WAIT1()  asm volatile("cp.async.wait_group 1;")

// ---------------- mma.sync m16n8k16 f16 (fp32 accum) ----------------
__device__ __forceinline__ void mma_f16(float* d, const uint32_t* a, const uint32_t* b) {
    asm volatile(
        "mma.sync.aligned.m16n8k16.row.col.f32.f16.f16.f32 "
        "{%0,%1,%2,%3}, {%4,%5,%6,%7}, {%8,%9}, {%0,%1,%2,%3};\n"
        : "+f"(d[0]), "+f"(d[1]), "+f"(d[2]), "+f"(d[3])
        : "r"(a[0]), "r"(a[1]), "r"(a[2]), "r"(a[3]), "r"(b[0]), "r"(b[1]));
}

// ================= ONE-SHOT K=256 GEMM: 128x64 tile ============================
#define LDL 264
#define SM256_BYTES ((128 + 64) * LDL * 2)   // 101376 B

__global__ void __launch_bounds__(256)
hgemm256_kernel(const __half* __restrict__ A, const __half* __restrict__ WT,
                const float* __restrict__ bias, const float* __restrict__ resid,
                float* __restrict__ C, __half* __restrict__ Ch, int N) {
    extern __shared__ __half hsm[];
    __half* Bsmem = hsm + 128 * LDL;

    const int t = threadIdx.x;
    const int lane = t & 31;
    const int wid  = t >> 5;
    const int wm = (wid & 3) * 32;
    const int wn = (wid >> 2) * 32;
    const int g   = lane >> 2;
    const int tig = lane & 3;
    const int row0 = blockIdx.y * 128;
    const int col0 = blockIdx.x * 64;

    const uint32_t as_u = (uint32_t)__cvta_generic_to_shared(hsm);
    const uint32_t bs_u = (uint32_t)__cvta_generic_to_shared(Bsmem);

    #pragma unroll
    for (int j = 0; j < 16; j++) {
        int slot = t + 256 * j;
        int r = slot >> 5, seg = slot & 31;
        cp_async16(as_u + (uint32_t)((r * LDL + seg * 8) * 2),
                   A + (size_t)(row0 + r) * 256 + seg * 8);
    }
    #pragma unroll
    for (int j = 0; j < 8; j++) {
        int slot = t + 256 * j;
        int r = slot >> 5, seg = slot & 31;
        cp_async16(bs_u + (uint32_t)((r * LDL + seg * 8) * 2),
                   WT + (size_t)(col0 + r) * 256 + seg * 8);
    }
    CP_COMMIT();

    float acc[2][4][4];
    #pragma unroll
    for (int i = 0; i < 2; i++)
        #pragma unroll
        for (int j = 0; j < 4; j++)
            #pragma unroll
            for (int r = 0; r < 4; r++) acc[i][j][r] = 0.f;

    CP_WAIT0();
    __syncthreads();

    #pragma unroll
    for (int ks = 0; ks < 16; ks++) {
        const int k0h = ks * 16;
        uint32_t bfr[4][2];
        #pragma unroll
        for (int nt = 0; nt < 4; nt++) {
            const __half* p = Bsmem + (wn + nt * 8 + g) * LDL + k0h + 2 * tig;
            bfr[nt][0] = *(const uint32_t*)(p);
            bfr[nt][1] = *(const uint32_t*)(p + 8);
        }
        #pragma unroll
        for (int mt = 0; mt < 2; mt++) {
            const __half* p = hsm + (wm + mt * 16 + g) * LDL + k0h + 2 * tig;
            uint32_t afr[4];
            afr[0] = *(const uint32_t*)(p);
            afr[1] = *(const uint32_t*)(p + 8 * LDL);
            afr[2] = *(const uint32_t*)(p + 8);
            afr[3] = *(const uint32_t*)(p + 8 * LDL + 8);
            #pragma unroll
            for (int nt = 0; nt < 4; nt++) mma_f16(acc[mt][nt], afr, bfr[nt]);
        }
    }

    #pragma unroll
    for (int mt = 0; mt < 2; mt++) {
        int r0 = row0 + wm + mt * 16 + g;
        #pragma unroll
        for (int nt = 0; nt < 4; nt++) {
            int cc = col0 + wn + nt * 8 + tig * 2;
            float2 bv = *(const float2*)(bias + cc);
            float2 v0, v1;
            v0.x = acc[mt][nt][0] + bv.x;
            v0.y = acc[mt][nt][1] + bv.y;
            v1.x = acc[mt][nt][2] + bv.x;
            v1.y = acc[mt][nt][3] + bv.y;
            if (resid) {
                float2 ra = *(const float2*)(resid + (size_t)r0 * N + cc);
                float2 rb = *(const float2*)(resid + (size_t)(r0 + 8) * N + cc);
                v0.x += ra.x; v0.y += ra.y;
                v1.x += rb.x; v1.y += rb.y;
            }
            if (C) {
                *(float2*)(C + (size_t)r0 * N + cc)       = v0;
                *(float2*)(C + (size_t)(r0 + 8) * N + cc) = v1;
            }
            if (Ch) {
                *(__half2*)(Ch + (size_t)r0 * N + cc)       = __floats2half2_rn(v0.x, v0.y);
                *(__half2*)(Ch + (size_t)(r0 + 8) * N + cc) = __floats2half2_rn(v1.x, v1.y);
            }
        }
    }
}

// ================= chunked 3-stage GEMM (for K=1024 fc2) =======================
#define LDH 40
#define STG 3
#define STAGE_A (128 * LDH)
#define STAGE_B (64 * LDH)

__global__ void __launch_bounds__(256)
hgemm_kernel(const __half* __restrict__ A, const __half* __restrict__ WT,
             const float* __restrict__ bias, const float* __restrict__ resid,
             float* __restrict__ C, __half* __restrict__ Ch, int N, int K) {
    extern __shared__ __half hsm[];
    __half* Bsmem = hsm + STG * STAGE_A;

    const int t = threadIdx.x;
    const int lane = t & 31;
    const int wid  = t >> 5;
    const int wm = (wid & 3) * 32;
    const int wn = (wid >> 2) * 32;
    const int g   = lane >> 2;
    const int tig = lane & 3;
    const int row0 = blockIdx.y * 128;
    const int col0 = blockIdx.x * 64;

    const uint32_t as_u = (uint32_t)__cvta_generic_to_shared(hsm);
    const uint32_t bs_u = (uint32_t)__cvta_generic_to_shared(Bsmem);

    float acc[2][4][4];
    #pragma unroll
    for (int i = 0; i < 2; i++)
        #pragma unroll
        for (int j = 0; j < 4; j++)
            #pragma unroll
            for (int r = 0; r < 4; r++) acc[i][j][r] = 0.f;

    const int NC = K >> 5;

    #pragma unroll
    for (int pc = 0; pc < 2; pc++) {
        const int k0 = pc << 5;
        const int soA = pc * STAGE_A;
        #pragma unroll
        for (int j = 0; j < 2; j++) {
            int slot = t + 256 * j;
            int r = slot >> 2, seg = slot & 3;
            cp_async16(as_u + (uint32_t)((soA + r * LDH + seg * 8) * 2),
                       A + (size_t)(row0 + r) * K + k0 + seg * 8);
        }
        const int soB = pc * STAGE_B;
        int r = t >> 2, seg = t & 3;
        cp_async16(bs_u + (uint32_t)((soB + r * LDH + seg * 8) * 2),
                   WT + (size_t)(col0 + r) * K + k0 + seg * 8);
        CP_COMMIT();
    }

    int stage = 0, pstage = 2;
    for (int c = 0; c < NC; c++) {
        if (c == NC - 1) { CP_WAIT0(); } else { CP_WAIT1(); }
        __syncthreads();
        if (c + 2 < NC) {
            const int k0 = (c + 2) << 5;
            const int soA = pstage * STAGE_A;
            #pragma unroll
            for (int j = 0; j < 2; j++) {
                int slot = t + 256 * j;
                int r = slot >> 2, seg = slot & 3;
                cp_async16(as_u + (uint32_t)((soA + r * LDH + seg * 8) * 2),
                           A + (size_t)(row0 + r) * K + k0 + seg * 8);
            }
            const int soB = pstage * STAGE_B;
            int r = t >> 2, seg = t & 3;
            cp_async16(bs_u + (uint32_t)((soB + r * LDH + seg * 8) * 2),
                       WT + (size_t)(col0 + r) * K + k0 + seg * 8);
            CP_COMMIT();
        }
        const __half* Asb = hsm   + stage * STAGE_A;
        const __half* Bsb = Bsmem + stage * STAGE_B;
        #pragma unroll
        for (int ks = 0; ks < 2; ks++) {
            const int k0h = ks * 16;
            uint32_t bfr[4][2];
            #pragma unroll
            for (int nt = 0; nt < 4; nt++) {
                const __half* p = Bsb + (wn + nt * 8 + g) * LDH + k0h + 2 * tig;
                bfr[nt][0] = *(const uint32_t*)(p);
                bfr[nt][1] = *(const uint32_t*)(p + 8);
            }
            #pragma unroll
            for (int mt = 0; mt < 2; mt++) {
                const __half* p = Asb + (wm + mt * 16 + g) * LDH + k0h + 2 * tig;
                uint32_t afr[4];
                afr[0] = *(const uint32_t*)(p);
                afr[1] = *(const uint32_t*)(p + 8 * LDH);
                afr[2] = *(const uint32_t*)(p + 8);
                afr[3] = *(const uint32_t*)(p + 8 * LDH + 8);
                #pragma unroll
                for (int nt = 0; nt < 4; nt++) mma_f16(acc[mt][nt], afr, bfr[nt]);
            }
        }
        stage = (stage == STG - 1) ? 0 : stage + 1;
        pstage = (pstage == STG - 1) ? 0 : pstage + 1;
    }
    __syncthreads();

    #pragma unroll
    for (int mt = 0; mt < 2; mt++) {
        int r0 = row0 + wm + mt * 16 + g;
        #pragma unroll
        for (int nt = 0; nt < 4; nt++) {
            int cc = col0 + wn + nt * 8 + tig * 2;
            float2 bv = *(const float2*)(bias + cc);
            float2 v0, v1;
            v0.x = acc[mt][nt][0] + bv.x;
            v0.y = acc[mt][nt][1] + bv.y;
            v1.x = acc[mt][nt][2] + bv.x;
            v1.y = acc[mt][nt][3] + bv.y;
            if (resid) {
                float2 ra = *(const float2*)(resid + (size_t)r0 * N + cc);
                float2 rb = *(const float2*)(resid + (size_t)(r0 + 8) * N + cc);
                v0.x += ra.x; v0.y += ra.y;
                v1.x += rb.x; v1.y += rb.y;
            }
            if (C) {
                *(float2*)(C + (size_t)r0 * N + cc)       = v0;
                *(float2*)(C + (size_t)(r0 + 8) * N + cc) = v1;
            }
            if (Ch) {
                *(__half2*)(Ch + (size_t)r0 * N + cc)       = __floats2half2_rn(v0.x, v0.y);
                *(__half2*)(Ch + (size_t)(r0 + 8) * N + cc) = __floats2half2_rn(v1.x, v1.y);
            }
        }
    }
}

#define GEMM_SMEM_BYTES ((unsigned)(STG * (STAGE_A + STAGE_B) * 2))   // 46080 B

// ---------------- combined transpose (fp32 -> half [N,K]) + bias concat ----------------
__global__ void __launch_bounds__(256)
transpose_all_kernel(const float* __restrict__ s_val, const float* __restrict__ s_off,
                     const float* __restrict__ s_attn, const float* __restrict__ s_out,
                     const float* __restrict__ s_fc1, const float* __restrict__ s_fc2,
                     const float* __restrict__ b_off, const float* __restrict__ b_attn,
                     __half* __restrict__ d_val, __half* __restrict__ d_offaw,
                     __half* __restrict__ d_out, __half* __restrict__ d_fc1,
                     __half* __restrict__ d_fc2, float* __restrict__ d_b_offaw) {
    int u = blockIdx.x;
    int t = threadIdx.x;
    if (u == 736) {
        if (t < 128) {
            d_b_offaw[t]       = b_off[t];
            d_b_offaw[t + 128] = b_off[t + 128];
        } else {
            int j = t - 128;
            d_b_offaw[256 + j] = b_attn[j];
        }
        return;
    }
    const float* src; __half* dst; int K, N;
    if      (u < 64)  {            src = s_val;  dst = d_val;             K = 256;  N = 256; }
    else if (u < 128) { u -= 64;   src = s_off;  dst = d_offaw;           K = 256;  N = 256; }
    else if (u < 160) { u -= 128;  src = s_attn; dst = d_offaw + 256*256; K = 256;  N = 128; }
    else if (u < 224) { u -= 160;  src = s_out;  dst = d_out;             K = 256;  N = 256; }
    else if (u < 480) { u -= 224;  src = s_fc1;  dst = d_fc1;             K = 256;  N = 1024; }
    else              { u -= 480;  src = s_fc2;  dst = d_fc2;             K = 1024; N = 256; }
    int nt = N >> 5;
    int by = (u / nt) * 32, bx = (u % nt) * 32;
    __shared__ float tile[32][33];
    int tx = t & 31, ty = t >> 5;
    #pragma unroll
    for (int i = 0; i < 32; i += 8)
        tile[ty + i][tx] = src[(size_t)(by + ty + i) * N + bx + tx];
    __syncthreads();
    #pragma unroll
    for (int i = 0; i < 32; i += 8)
        dst[(size_t)(bx + ty + i) * K + by + tx] = __float2half_rn(tile[tx][ty + i]);
}

// ---------------- combined flatten: q -> half + fp32, v -> fp32 ----------------
__global__ void __launch_bounds__(256)
flatten_all_kernel(const float* __restrict__ q0, const float* __restrict__ v0,
                   const float* __restrict__ q1, const float* __restrict__ v1,
                   const float* __restrict__ q2, const float* __restrict__ v2,
                   const float* __restrict__ q3, const float* __restrict__ v3,
                   __half* __restrict__ gqh, float* __restrict__ gq32,
                   float* __restrict__ gv) {
    __shared__ float tq[32][33], tv[32][33];
    int blk = blockIdx.x;
    int b = blk / 1360;
    int u = blk % 1360;
    const float *qs, *vs; int n, start;
    if      (u < 1024) {            qs = q0; vs = v0; n = 4096; start = 0; }
    else if (u < 1280) { u -= 1024; qs = q1; vs = v1; n = 1024; start = 4096; }
    else if (u < 1344) { u -= 1280; qs = q2; vs = v2; n = 256;  start = 5120; }
    else               { u -= 1344; qs = q3; vs = v3; n = 64;   start = 5376; }
    int pt = n >> 5;
    int ct = u / pt;
    int pi = u % pt;
    int t = threadIdx.x;
    int tx = t & 31, ty = t >> 5;
    const float* qb = qs + (size_t)(b * DIM + ct * 32) * n + pi * 32;
    const float* vb = vs + (size_t)(b * DIM + ct * 32) * n + pi * 32;
    #pragma unroll
    for (int i = 0; i < 32; i += 8) {
        tq[ty + i][tx] = qb[(size_t)(ty + i) * n + tx];
        tv[ty + i][tx] = vb[(size_t)(ty + i) * n + tx];
    }
    __syncthreads();
    size_t obase = ((size_t)b * NQ + start + pi * 32) * DIM + ct * 32;
    #pragma unroll
    for (int i = 0; i < 32; i += 8) {
        float qv = tq[tx][ty + i];
        gq32[obase + (size_t)(ty + i) * DIM + tx] = qv;
        gqh [obase + (size_t)(ty + i) * DIM + tx] = __float2half_rn(qv);
        gv  [obase + (size_t)(ty + i) * DIM + tx] = tv[tx][ty + i];
    }
}

// ---------------- layernorm (fp32 in, half out) ----------------
__global__ void layernorm_kernel(const float* __restrict__ x, const float* __restrict__ g,
                                 const float* __restrict__ bia, __half* __restrict__ out) {
    int row = blockIdx.x;
    int t = threadIdx.x;
    float v = x[(size_t)row * DIM + t];
    __shared__ float sm[40];
    float s = v;
    #pragma unroll
    for (int o = 16; o > 0; o >>= 1) s += __shfl_xor_sync(0xffffffffu, s, o);
    if ((t & 31) == 0) sm[t >> 5] = s;
    __syncthreads();
    if (t < 8) {
        float z = sm[t];
        #pragma unroll
        for (int o = 4; o > 0; o >>= 1) z += __shfl_xor_sync(0xffu, z, o);
        if (t == 0) sm[32] = z;
    }
    __syncthreads();
    float mean = sm[32] * (1.0f / DIM);
    float d = v - mean;
    float s2 = d * d;
    #pragma unroll
    for (int o = 16; o > 0; o >>= 1) s2 += __shfl_xor_sync(0xffffffffu, s2, o);
    if ((t & 31) == 0) sm[8 + (t >> 5)] = s2;
    __syncthreads();
    if (t < 8) {
        float z = sm[8 + t];
        #pragma unroll
        for (int o = 4; o > 0; o >>= 1) z += __shfl_xor_sync(0xffu, z, o);
        if (t == 0) sm[33] = z;
    }
    __syncthreads();
    float var = sm[33] * (1.0f / DIM);
    out[(size_t)row * DIM + t] = __float2half_rn(d * rsqrtf(var + 1e-5f) * g[t] + bia[t]);
}

// ---------------- deformable sampling, fused softmax, HALF val ---------------
__global__ void __launch_bounds__(256)
deform_kernel(const __half* __restrict__ val, const float* __restrict__ offaw,
              __half* __restrict__ samp) {
    int gw = (blockIdx.x * blockDim.x + threadIdx.x) >> 5;
    int lane = threadIdx.x & 31;
    if (gw >= MROWS * NH) return;
    int hh = gw % NH;
    int q  = (gw / NH) % NQ;
    int b  = gw / (NH * NQ);

    int lqv, local;
    if (q < 4096)      { lqv = 0; local = q; }
    else if (q < 5120) { lqv = 1; local = q - 4096; }
    else if (q < 5376) { lqv = 2; local = q - 5120; }
    else               { lqv = 3; local = q - 5376; }
    int szq = LVL_SIZE[lqv];
    float refx = ((local % szq) + 0.5f) / szq;
    float refy = ((local / szq) + 0.5f) / szq;

    const float* rowp = offaw + (size_t)(b * NQ + q) * 384;
    const float* offp = rowp + hh * 32;
    const float* awp  = rowp + 256 + hh * 16;

    float awv[16];
    float mx = -1e30f;
    #pragma unroll
    for (int j = 0; j < 16; j++) { awv[j] = awp[j]; mx = fmaxf(mx, awv[j]); }
    float ssum = 0.f;
    #pragma unroll
    for (int j = 0; j < 16; j++) { awv[j] = __expf(awv[j] - mx); ssum += awv[j]; }
    float sinv = 1.0f / ssum;

    float acc = 0.f;
    #pragma unroll
    for (int l = 0; l < NL; l++) {
        int w = LVL_SIZE[l];
        int startl = LVL_START[l];
        const __half* vbase = val + ((size_t)b * NQ + startl) * DIM + hh * HD + lane;
        float inv = 1.0f / (float)w;
        #pragma unroll
        for (int p = 0; p < NP; p++) {
            float ox = offp[(l * NP + p) * 2 + 0];
            float oy = offp[(l * NP + p) * 2 + 1];
            float a  = awv[l * NP + p] * sinv;
            float sx = (refx + ox * inv) * w - 0.5f;
            float sy = (refy + oy * inv) * w - 0.5f;
            int x0 = (int)floorf(sx);
            int y0 = (int)floorf(sy);
            float lx = sx - (float)x0;
            float ly = sy - (float)y0;
            float w00 = (1.f - lx) * (1.f - ly);
            float w10 = lx * (1.f - ly);
            float w01 = (1.f - lx) * ly;
            float w11 = lx * ly;
            float g = 0.f;
            if (x0 >= 0 && x0 < w && y0 >= 0 && y0 < w)
                g += w00 * __half2float(vbase[(size_t)(y0 * w + x0) * DIM]);
            if (x0 + 1 >= 0 && x0 + 1 < w && y0 >= 0 && y0 < w)
                g += w10 * __half2float(vbase[(size_t)(y0 * w + x0 + 1) * DIM]);
            if (x0 >= 0 && x0 < w && y0 + 1 >= 0 && y0 + 1 < w)
                g += w01 * __half2float(vbase[(size_t)((y0 + 1) * w + x0) * DIM]);
            if (x0 + 1 >= 0 && x0 + 1 < w && y0 + 1 >= 0 && y0 + 1 < w)
                g += w11 * __half2float(vbase[(size_t)((y0 + 1) * w + x0 + 1) * DIM]);
            acc = fmaf(a, g, acc);
        }
    }
    samp[(size_t)(b * NQ + q) * DIM + hh * HD + lane] = __float2half_rn(acc);
}

// ---------------- depthwise 3x3 + bias + GELU (HALF in, half out) -------------
__global__ void __launch_bounds__(256)
dwconv_gelu_tiled(const __half* __restrict__ h1, const float* __restrict__ Wdw,
                  const float* __restrict__ bdw, __half* __restrict__ h2) {
    extern __shared__ float ts[];   // [100][128]
    int tile = blockIdx.x;
    int c0 = blockIdx.y * 128;
    int b = blockIdx.z;
    int l, tx, ty;
    if      (tile < 64) { l = 0; ty = tile >> 3; tx = tile & 7; }
    else if (tile < 80) { int u = tile - 64; l = 1; ty = u >> 2; tx = u & 3; }
    else if (tile < 84) { int u = tile - 80; l = 2; ty = u >> 1; tx = u & 1; }
    else                { l = 3; ty = 0; tx = 0; }
    int w = LVL_SIZE[l];
    int start = LVL_START[l];
    int t = threadIdx.x;
    int c = t & 127;
    int half = t >> 7;

    const __half* hbase = h1 + ((size_t)b * NQ + start) * HID + c0 + c;
    for (int p = half; p < 100; p += 2) {
        int py = p / 10 - 1 + ty * 8;
        int px = p % 10 - 1 + tx * 8;
        float v = 0.f;
        if (py >= 0 && py < w && px >= 0 && px < w)
            v = __half2float(hbase[(size_t)(py * w + px) * HID]);
        ts[p * 128 + c] = v;
    }
    float w9[9];
    #pragma unroll
    for (int j = 0; j < 9; j++) w9[j] = Wdw[j * HID + c0 + c];
    float bs = bdw[c0 + c];
    __syncthreads();

    __half* obase = h2 + ((size_t)b * NQ + start + (ty * 8) * w + tx * 8) * HID + c0 + c;
    for (int p = half; p < 64; p += 2) {
        int py = p >> 3, px = p & 7;
        float acc = bs;
        #pragma unroll
        for (int ky = 0; ky < 3; ky++)
            #pragma unroll
            for (int kx = 0; kx < 3; kx++)
                acc = fmaf(ts[((py + ky) * 10 + px + kx) * 128 + c], w9[ky * 3 + kx], acc);
        float gelu = acc * 0.5f * (1.0f + erff(acc * 0.70710678118654752440f));
        obase[(size_t)(py * w + px) * HID] = __float2half_rn(gelu);
    }
}
#define DW_SMEM_BYTES (100u * 128u * 4u)   // 51200

// ---------------- launch ----------------
extern "C" void kernel_launch(void* const* d_in, const int* in_sizes, int n_in,
                              void* d_out, int out_size) {
    const float* q0 = (const float*)d_in[0];
    const float* v0 = (const float*)d_in[1];
    const float* q1 = (const float*)d_in[2];
    const float* v1 = (const float*)d_in[3];
    const float* q2 = (const float*)d_in[4];
    const float* v2 = (const float*)d_in[5];
    const float* q3 = (const float*)d_in[6];
    const float* v3 = (const float*)d_in[7];
    const float* vn_g  = (const float*)d_in[8];
    const float* vn_b  = (const float*)d_in[9];
    const float* W_off = (const float*)d_in[10];
    const float* b_off = (const float*)d_in[11];
    const float* W_attn= (const float*)d_in[12];
    const float* b_attn= (const float*)d_in[13];
    const float* W_val = (const float*)d_in[14];
    const float* b_val = (const float*)d_in[15];
    const float* W_out = (const float*)d_in[16];
    const float* b_out = (const float*)d_in[17];
    const float* W_fc1 = (const float*)d_in[18];
    const float* b_fc1 = (const float*)d_in[19];
    const float* W_dw  = (const float*)d_in[20];
    const float* b_dw  = (const float*)d_in[21];
    const float* W_fc2 = (const float*)d_in[22];
    const float* b_fc2 = (const float*)d_in[23];
    float* out = (float*)d_out;

    __half *gqh, *gvnh, *gvalh, *gsamph, *gxh, *gh1h, *gh2h;
    __half *wtval, *wtoffaw, *wtout, *wtfc1, *wtfc2;
    float *gq32, *gv, *goffaw, *gx, *boffaw;
    cudaGetSymbolAddress((void**)&gqh,    g_qh);
    cudaGetSymbolAddress((void**)&gq32,   g_q32);
    cudaGetSymbolAddress((void**)&gv,     g_value);
    cudaGetSymbolAddress((void**)&gvnh,   g_vnh);
    cudaGetSymbolAddress((void**)&gvalh,  g_valh);
    cudaGetSymbolAddress((void**)&goffaw, g_offaw);
    cudaGetSymbolAddress((void**)&gsamph, g_samph);
    cudaGetSymbolAddress((void**)&gx,     g_x);
    cudaGetSymbolAddress((void**)&gxh,    g_xh);
    cudaGetSymbolAddress((void**)&gh1h,   g_h1h);
    cudaGetSymbolAddress((void**)&gh2h,   g_h2h);
    cudaGetSymbolAddress((void**)&wtval,  g_WT_val);
    cudaGetSymbolAddress((void**)&wtoffaw,g_WT_offaw);
    cudaGetSymbolAddress((void**)&boffaw, g_b_offaw);
    cudaGetSymbolAddress((void**)&wtout,  g_WT_out);
    cudaGetSymbolAddress((void**)&wtfc1,  g_WT_fc1);
    cudaGetSymbolAddress((void**)&wtfc2,  g_WT_fc2);

    cudaFuncSetAttribute(hgemm256_kernel,
                         cudaFuncAttributeMaxDynamicSharedMemorySize, SM256_BYTES);
    cudaFuncSetAttribute(hgemm_kernel,
                         cudaFuncAttributeMaxDynamicSharedMemorySize, GEMM_SMEM_BYTES);
    cudaFuncSetAttribute(dwconv_gelu_tiled,
                         cudaFuncAttributeMaxDynamicSharedMemorySize, DW_SMEM_BYTES);

    transpose_all_kernel<<<737, 256>>>(W_val, W_off, W_attn, W_out, W_fc1, W_fc2,
                                       b_off, b_attn,
                                       wtval, wtoffaw, wtout, wtfc1, wtfc2, boffaw);

    flatten_all_kernel<<<2720, 256>>>(q0, v0, q1, v1, q2, v2, q3, v3, gqh, gq32, gv);

    layernorm_kernel<<<MROWS, 256>>>(gv, vn_g, vn_b, gvnh);

    const int MT = MROWS / 128;  // 85
    // val (HALF only) = LN(value) @ W_val + b_val
    hgemm256_kernel<<<dim3(DIM / 64, MT), 256, SM256_BYTES>>>(gvnh, wtval, b_val, nullptr,
                                                              nullptr, gvalh, DIM);
    // [off | aw_raw] = query @ [W_off | W_attn] + [b_off | b_attn]
    hgemm256_kernel<<<dim3(384 / 64, MT), 256, SM256_BYTES>>>(gqh, wtoffaw, boffaw, nullptr,
                                                              goffaw, nullptr, 384);

    // sampling (softmax fused), half val in, half samp out
    deform_kernel<<<(MROWS * NH * 32 + 255) / 256, 256>>>(gvalh, goffaw, gsamph);

    // x = query + samp @ W_out + b_out   (fp32 + half outputs)
    hgemm256_kernel<<<dim3(DIM / 64, MT), 256, SM256_BYTES>>>(gsamph, wtout, b_out, gq32,
                                                              gx, gxh, DIM);
    // h1 (HALF only) = x @ W_fc1 + b_fc1
    hgemm256_kernel<<<dim3(HID / 64, MT), 256, SM256_BYTES>>>(gxh, wtfc1, b_fc1, nullptr,
                                                              nullptr, gh1h, HID);

    // h2 = gelu(dwconv(h1) + b_dw), half in/out
    dwconv_gelu_tiled<<<dim3(85, 8, BB), 256, DW_SMEM_BYTES>>>(gh1h, W_dw, b_dw, gh2h);

    // out = x + h2 @ W_fc2 + b_fc2  (K=1024, chunked pipeline)
    hgemm_kernel<<<dim3(DIM / 64, MT), 256, GEMM_SMEM_BYTES>>>(gh2h, wtfc2, b_fc2, gx,
                                                               out, nullptr, DIM, HID);
}

// round 15
// speedup vs baseline: 1.1053x; 1.1053x over previous
#include <cuda_runtime.h>
#include <cuda_fp16.h>
#include <math.h>
#include <stdint.h>

// ---------------- problem constants ----------------
#define BB   2
#define DIM  256
#define NH   8
#define HD   32
#define NL   4
#define NP   4
#define HID  1024
#define NQ   5440
#define MROWS (BB*NQ)   // 10880 = 85*128

__device__ __constant__ int LVL_SIZE[4]  = {64, 32, 16, 8};
__device__ __constant__ int LVL_START[4] = {0, 4096, 5120, 5376};

// ---------------- scratch ----------------
__device__ __half g_qh   [(size_t)MROWS * DIM];
__device__ float  g_q32  [(size_t)MROWS * DIM];
__device__ float  g_value[(size_t)MROWS * DIM];
__device__ __half g_vnh  [(size_t)MROWS * DIM];
__device__ __half g_valh [(size_t)MROWS * DIM];     // val in HALF (deform input)
__device__ float  g_offaw[(size_t)MROWS * 384];
__device__ __half g_samph[(size_t)MROWS * DIM];
__device__ float  g_x    [(size_t)MROWS * DIM];
__device__ __half g_xh   [(size_t)MROWS * DIM];
__device__ __half g_h1h  [(size_t)MROWS * HID];     // h1 in HALF (dwconv input)
__device__ __half g_h2h  [(size_t)MROWS * HID];
// transposed weights [N, K] in half
__device__ __half g_WT_val  [DIM * DIM];
__device__ __half g_WT_offaw[384 * DIM];
__device__ float  g_b_offaw [384];
__device__ __half g_WT_out  [DIM * DIM];
__device__ __half g_WT_fc1  [HID * DIM];
__device__ __half g_WT_fc2  [DIM * HID];

// ---------------- cp.async helpers ----------------
__device__ __forceinline__ void cp_async16(uint32_t smem, const void* gmem) {
    asm volatile("cp.async.cg.shared.global [%0], [%1], 16;" :: "r"(smem), "l"(gmem));
}
#define CP_COMMIT() asm volatile("cp.async.commit_group;")
#define CP_WAIT0()  asm volatile("cp.async.wait_group 0;")
#define CP_WAIT1()  asm volatile("cp.async.wait_group 1;")

// ---------------- mma.sync m16n8k16 f16 (fp32 accum) ----------------
__device__ __forceinline__ void mma_f16(float* d, const uint32_t* a, const uint32_t* b) {
    asm volatile(
        "mma.sync.aligned.m16n8k16.row.col.f32.f16.f16.f32 "
        "{%0,%1,%2,%3}, {%4,%5,%6,%7}, {%8,%9}, {%0,%1,%2,%3};\n"
        : "+f"(d[0]), "+f"(d[1]), "+f"(d[2]), "+f"(d[3])
        : "r"(a[0]), "r"(a[1]), "r"(a[2]), "r"(a[3]), "r"(b[0]), "r"(b[1]));
}

// ================= ONE-SHOT K=256 GEMM: 128x64 tile ============================
#define LDL 264
#define SM256_BYTES ((128 + 64) * LDL * 2)   // 101376 B

__global__ void __launch_bounds__(256)
hgemm256_kernel(const __half* __restrict__ A, const __half* __restrict__ WT,
                const float* __restrict__ bias, const float* __restrict__ resid,
                float* __restrict__ C, __half* __restrict__ Ch, int N) {
    extern __shared__ __half hsm[];
    __half* Bsmem = hsm + 128 * LDL;

    const int t = threadIdx.x;
    const int lane = t & 31;
    const int wid  = t >> 5;
    const int wm = (wid & 3) * 32;
    const int wn = (wid >> 2) * 32;
    const int g   = lane >> 2;
    const int tig = lane & 3;
    const int row0 = blockIdx.y * 128;
    const int col0 = blockIdx.x * 64;

    const uint32_t as_u = (uint32_t)__cvta_generic_to_shared(hsm);
    const uint32_t bs_u = (uint32_t)__cvta_generic_to_shared(Bsmem);

    #pragma unroll
    for (int j = 0; j < 16; j++) {
        int slot = t + 256 * j;
        int r = slot >> 5, seg = slot & 31;
        cp_async16(as_u + (uint32_t)((r * LDL + seg * 8) * 2),
                   A + (size_t)(row0 + r) * 256 + seg * 8);
    }
    #pragma unroll
    for (int j = 0; j < 8; j++) {
        int slot = t + 256 * j;
        int r = slot >> 5, seg = slot & 31;
        cp_async16(bs_u + (uint32_t)((r * LDL + seg * 8) * 2),
                   WT + (size_t)(col0 + r) * 256 + seg * 8);
    }
    CP_COMMIT();

    float acc[2][4][4];
    #pragma unroll
    for (int i = 0; i < 2; i++)
        #pragma unroll
        for (int j = 0; j < 4; j++)
            #pragma unroll
            for (int r = 0; r < 4; r++) acc[i][j][r] = 0.f;

    CP_WAIT0();
    __syncthreads();

    #pragma unroll
    for (int ks = 0; ks < 16; ks++) {
        const int k0h = ks * 16;
        uint32_t bfr[4][2];
        #pragma unroll
        for (int nt = 0; nt < 4; nt++) {
            const __half* p = Bsmem + (wn + nt * 8 + g) * LDL + k0h + 2 * tig;
            bfr[nt][0] = *(const uint32_t*)(p);
            bfr[nt][1] = *(const uint32_t*)(p + 8);
        }
        #pragma unroll
        for (int mt = 0; mt < 2; mt++) {
            const __half* p = hsm + (wm + mt * 16 + g) * LDL + k0h + 2 * tig;
            uint32_t afr[4];
            afr[0] = *(const uint32_t*)(p);
            afr[1] = *(const uint32_t*)(p + 8 * LDL);
            afr[2] = *(const uint32_t*)(p + 8);
            afr[3] = *(const uint32_t*)(p + 8 * LDL + 8);
            #pragma unroll
            for (int nt = 0; nt < 4; nt++) mma_f16(acc[mt][nt], afr, bfr[nt]);
        }
    }

    #pragma unroll
    for (int mt = 0; mt < 2; mt++) {
        int r0 = row0 + wm + mt * 16 + g;
        #pragma unroll
        for (int nt = 0; nt < 4; nt++) {
            int cc = col0 + wn + nt * 8 + tig * 2;
            float2 bv = *(const float2*)(bias + cc);
            float2 v0, v1;
            v0.x = acc[mt][nt][0] + bv.x;
            v0.y = acc[mt][nt][1] + bv.y;
            v1.x = acc[mt][nt][2] + bv.x;
            v1.y = acc[mt][nt][3] + bv.y;
            if (resid) {
                float2 ra = *(const float2*)(resid + (size_t)r0 * N + cc);
                float2 rb = *(const float2*)(resid + (size_t)(r0 + 8) * N + cc);
                v0.x += ra.x; v0.y += ra.y;
                v1.x += rb.x; v1.y += rb.y;
            }
            if (C) {
                *(float2*)(C + (size_t)r0 * N + cc)       = v0;
                *(float2*)(C + (size_t)(r0 + 8) * N + cc) = v1;
            }
            if (Ch) {
                *(__half2*)(Ch + (size_t)r0 * N + cc)       = __floats2half2_rn(v0.x, v0.y);
                *(__half2*)(Ch + (size_t)(r0 + 8) * N + cc) = __floats2half2_rn(v1.x, v1.y);
            }
        }
    }
}

// ================= chunked 3-stage GEMM (for K=1024 fc2) =======================
#define LDH 40
#define STG 3
#define STAGE_A (128 * LDH)
#define STAGE_B (64 * LDH)

__global__ void __launch_bounds__(256)
hgemm_kernel(const __half* __restrict__ A, const __half* __restrict__ WT,
             const float* __restrict__ bias, const float* __restrict__ resid,
             float* __restrict__ C, __half* __restrict__ Ch, int N, int K) {
    extern __shared__ __half hsm[];
    __half* Bsmem = hsm + STG * STAGE_A;

    const int t = threadIdx.x;
    const int lane = t & 31;
    const int wid  = t >> 5;
    const int wm = (wid & 3) * 32;
    const int wn = (wid >> 2) * 32;
    const int g   = lane >> 2;
    const int tig = lane & 3;
    const int row0 = blockIdx.y * 128;
    const int col0 = blockIdx.x * 64;

    const uint32_t as_u = (uint32_t)__cvta_generic_to_shared(hsm);
    const uint32_t bs_u = (uint32_t)__cvta_generic_to_shared(Bsmem);

    float acc[2][4][4];
    #pragma unroll
    for (int i = 0; i < 2; i++)
        #pragma unroll
        for (int j = 0; j < 4; j++)
            #pragma unroll
            for (int r = 0; r < 4; r++) acc[i][j][r] = 0.f;

    const int NC = K >> 5;

    #pragma unroll
    for (int pc = 0; pc < 2; pc++) {
        const int k0 = pc << 5;
        const int soA = pc * STAGE_A;
        #pragma unroll
        for (int j = 0; j < 2; j++) {
            int slot = t + 256 * j;
            int r = slot >> 2, seg = slot & 3;
            cp_async16(as_u + (uint32_t)((soA + r * LDH + seg * 8) * 2),
                       A + (size_t)(row0 + r) * K + k0 + seg * 8);
        }
        const int soB = pc * STAGE_B;
        int r = t >> 2, seg = t & 3;
        cp_async16(bs_u + (uint32_t)((soB + r * LDH + seg * 8) * 2),
                   WT + (size_t)(col0 + r) * K + k0 + seg * 8);
        CP_COMMIT();
    }

    int stage = 0, pstage = 2;
    for (int c = 0; c < NC; c++) {
        if (c == NC - 1) { CP_WAIT0(); } else { CP_WAIT1(); }
        __syncthreads();
        if (c + 2 < NC) {
            const int k0 = (c + 2) << 5;
            const int soA = pstage * STAGE_A;
            #pragma unroll
            for (int j = 0; j < 2; j++) {
                int slot = t + 256 * j;
                int r = slot >> 2, seg = slot & 3;
                cp_async16(as_u + (uint32_t)((soA + r * LDH + seg * 8) * 2),
                           A + (size_t)(row0 + r) * K + k0 + seg * 8);
            }
            const int soB = pstage * STAGE_B;
            int r = t >> 2, seg = t & 3;
            cp_async16(bs_u + (uint32_t)((soB + r * LDH + seg * 8) * 2),
                       WT + (size_t)(col0 + r) * K + k0 + seg * 8);
            CP_COMMIT();
        }
        const __half* Asb = hsm   + stage * STAGE_A;
        const __half* Bsb = Bsmem + stage * STAGE_B;
        #pragma unroll
        for (int ks = 0; ks < 2; ks++) {
            const int k0h = ks * 16;
            uint32_t bfr[4][2];
            #pragma unroll
            for (int nt = 0; nt < 4; nt++) {
                const __half* p = Bsb + (wn + nt * 8 + g) * LDH + k0h + 2 * tig;
                bfr[nt][0] = *(const uint32_t*)(p);
                bfr[nt][1] = *(const uint32_t*)(p + 8);
            }
            #pragma unroll
            for (int mt = 0; mt < 2; mt++) {
                const __half* p = Asb + (wm + mt * 16 + g) * LDH + k0h + 2 * tig;
                uint32_t afr[4];
                afr[0] = *(const uint32_t*)(p);
                afr[1] = *(const uint32_t*)(p + 8 * LDH);
                afr[2] = *(const uint32_t*)(p + 8);
                afr[3] = *(const uint32_t*)(p + 8 * LDH + 8);
                #pragma unroll
                for (int nt = 0; nt < 4; nt++) mma_f16(acc[mt][nt], afr, bfr[nt]);
            }
        }
        stage = (stage == STG - 1) ? 0 : stage + 1;
        pstage = (pstage == STG - 1) ? 0 : pstage + 1;
    }
    __syncthreads();

    #pragma unroll
    for (int mt = 0; mt < 2; mt++) {
        int r0 = row0 + wm + mt * 16 + g;
        #pragma unroll
        for (int nt = 0; nt < 4; nt++) {
            int cc = col0 + wn + nt * 8 + tig * 2;
            float2 bv = *(const float2*)(bias + cc);
            float2 v0, v1;
            v0.x = acc[mt][nt][0] + bv.x;
            v0.y = acc[mt][nt][1] + bv.y;
            v1.x = acc[mt][nt][2] + bv.x;
            v1.y = acc[mt][nt][3] + bv.y;
            if (resid) {
                float2 ra = *(const float2*)(resid + (size_t)r0 * N + cc);
                float2 rb = *(const float2*)(resid + (size_t)(r0 + 8) * N + cc);
                v0.x += ra.x; v0.y += ra.y;
                v1.x += rb.x; v1.y += rb.y;
            }
            if (C) {
                *(float2*)(C + (size_t)r0 * N + cc)       = v0;
                *(float2*)(C + (size_t)(r0 + 8) * N + cc) = v1;
            }
            if (Ch) {
                *(__half2*)(Ch + (size_t)r0 * N + cc)       = __floats2half2_rn(v0.x, v0.y);
                *(__half2*)(Ch + (size_t)(r0 + 8) * N + cc) = __floats2half2_rn(v1.x, v1.y);
            }
        }
    }
}

#define GEMM_SMEM_BYTES ((unsigned)(STG * (STAGE_A + STAGE_B) * 2))   // 46080 B

// ---------------- combined transpose (fp32 -> half [N,K]) + bias concat ----------------
__global__ void __launch_bounds__(256)
transpose_all_kernel(const float* __restrict__ s_val, const float* __restrict__ s_off,
                     const float* __restrict__ s_attn, const float* __restrict__ s_out,
                     const float* __restrict__ s_fc1, const float* __restrict__ s_fc2,
                     const float* __restrict__ b_off, const float* __restrict__ b_attn,
                     __half* __restrict__ d_val, __half* __restrict__ d_offaw,
                     __half* __restrict__ d_out, __half* __restrict__ d_fc1,
                     __half* __restrict__ d_fc2, float* __restrict__ d_b_offaw) {
    int u = blockIdx.x;
    int t = threadIdx.x;
    if (u == 736) {
        if (t < 128) {
            d_b_offaw[t]       = b_off[t];
            d_b_offaw[t + 128] = b_off[t + 128];
        } else {
            int j = t - 128;
            d_b_offaw[256 + j] = b_attn[j];
        }
        return;
    }
    const float* src; __half* dst; int K, N;
    if      (u < 64)  {            src = s_val;  dst = d_val;             K = 256;  N = 256; }
    else if (u < 128) { u -= 64;   src = s_off;  dst = d_offaw;           K = 256;  N = 256; }
    else if (u < 160) { u -= 128;  src = s_attn; dst = d_offaw + 256*256; K = 256;  N = 128; }
    else if (u < 224) { u -= 160;  src = s_out;  dst = d_out;             K = 256;  N = 256; }
    else if (u < 480) { u -= 224;  src = s_fc1;  dst = d_fc1;             K = 256;  N = 1024; }
    else              { u -= 480;  src = s_fc2;  dst = d_fc2;             K = 1024; N = 256; }
    int nt = N >> 5;
    int by = (u / nt) * 32, bx = (u % nt) * 32;
    __shared__ float tile[32][33];
    int tx = t & 31, ty = t >> 5;
    #pragma unroll
    for (int i = 0; i < 32; i += 8)
        tile[ty + i][tx] = src[(size_t)(by + ty + i) * N + bx + tx];
    __syncthreads();
    #pragma unroll
    for (int i = 0; i < 32; i += 8)
        dst[(size_t)(bx + ty + i) * K + by + tx] = __float2half_rn(tile[tx][ty + i]);
}

// ---------------- combined flatten: q -> half + fp32, v -> fp32 ----------------
__global__ void __launch_bounds__(256)
flatten_all_kernel(const float* __restrict__ q0, const float* __restrict__ v0,
                   const float* __restrict__ q1, const float* __restrict__ v1,
                   const float* __restrict__ q2, const float* __restrict__ v2,
                   const float* __restrict__ q3, const float* __restrict__ v3,
                   __half* __restrict__ gqh, float* __restrict__ gq32,
                   float* __restrict__ gv) {
    __shared__ float tq[32][33], tv[32][33];
    int blk = blockIdx.x;
    int b = blk / 1360;
    int u = blk % 1360;
    const float *qs, *vs; int n, start;
    if      (u < 1024) {            qs = q0; vs = v0; n = 4096; start = 0; }
    else if (u < 1280) { u -= 1024; qs = q1; vs = v1; n = 1024; start = 4096; }
    else if (u < 1344) { u -= 1280; qs = q2; vs = v2; n = 256;  start = 5120; }
    else               { u -= 1344; qs = q3; vs = v3; n = 64;   start = 5376; }
    int pt = n >> 5;
    int ct = u / pt;
    int pi = u % pt;
    int t = threadIdx.x;
    int tx = t & 31, ty = t >> 5;
    const float* qb = qs + (size_t)(b * DIM + ct * 32) * n + pi * 32;
    const float* vb = vs + (size_t)(b * DIM + ct * 32) * n + pi * 32;
    #pragma unroll
    for (int i = 0; i < 32; i += 8) {
        tq[ty + i][tx] = qb[(size_t)(ty + i) * n + tx];
        tv[ty + i][tx] = vb[(size_t)(ty + i) * n + tx];
    }
    __syncthreads();
    size_t obase = ((size_t)b * NQ + start + pi * 32) * DIM + ct * 32;
    #pragma unroll
    for (int i = 0; i < 32; i += 8) {
        float qv = tq[tx][ty + i];
        gq32[obase + (size_t)(ty + i) * DIM + tx] = qv;
        gqh [obase + (size_t)(ty + i) * DIM + tx] = __float2half_rn(qv);
        gv  [obase + (size_t)(ty + i) * DIM + tx] = tv[tx][ty + i];
    }
}

// ---------------- layernorm (fp32 in, half out) ----------------
__global__ void layernorm_kernel(const float* __restrict__ x, const float* __restrict__ g,
                                 const float* __restrict__ bia, __half* __restrict__ out) {
    int row = blockIdx.x;
    int t = threadIdx.x;
    float v = x[(size_t)row * DIM + t];
    __shared__ float sm[40];
    float s = v;
    #pragma unroll
    for (int o = 16; o > 0; o >>= 1) s += __shfl_xor_sync(0xffffffffu, s, o);
    if ((t & 31) == 0) sm[t >> 5] = s;
    __syncthreads();
    if (t < 8) {
        float z = sm[t];
        #pragma unroll
        for (int o = 4; o > 0; o >>= 1) z += __shfl_xor_sync(0xffu, z, o);
        if (t == 0) sm[32] = z;
    }
    __syncthreads();
    float mean = sm[32] * (1.0f / DIM);
    float d = v - mean;
    float s2 = d * d;
    #pragma unroll
    for (int o = 16; o > 0; o >>= 1) s2 += __shfl_xor_sync(0xffffffffu, s2, o);
    if ((t & 31) == 0) sm[8 + (t >> 5)] = s2;
    __syncthreads();
    if (t < 8) {
        float z = sm[8 + t];
        #pragma unroll
        for (int o = 4; o > 0; o >>= 1) z += __shfl_xor_sync(0xffu, z, o);
        if (t == 0) sm[33] = z;
    }
    __syncthreads();
    float var = sm[33] * (1.0f / DIM);
    out[(size_t)row * DIM + t] = __float2half_rn(d * rsqrtf(var + 1e-5f) * g[t] + bia[t]);
}

// ---------------- deformable sampling v2: lane-split params, half2 gathers -----
// warp = (b, q, head). half = lane>>4 selects point parity; c2 = lane&15 covers
// the head's 32 channels as 16 half2. One gather LDG serves TWO sample points.
__global__ void __launch_bounds__(256)
deform_kernel(const __half* __restrict__ val, const float* __restrict__ offaw,
              __half* __restrict__ samp) {
    const unsigned FULL = 0xffffffffu;
    int gw = (blockIdx.x * blockDim.x + threadIdx.x) >> 5;
    int lane = threadIdx.x & 31;
    if (gw >= MROWS * NH) return;
    int hh = gw % NH;
    int q  = (gw / NH) % NQ;
    int b  = gw / (NH * NQ);
    int ph = lane >> 4;      // point parity handled by this half-warp
    int c2 = lane & 15;      // half2 channel index

    int lqv, local;
    if (q < 4096)      { lqv = 0; local = q; }
    else if (q < 5120) { lqv = 1; local = q - 4096; }
    else if (q < 5376) { lqv = 2; local = q - 5120; }
    else               { lqv = 3; local = q - 5376; }
    int szq = LVL_SIZE[lqv];
    float refx = ((local % szq) + 0.5f) / szq;
    float refy = ((local / szq) + 0.5f) / szq;

    const float* rowp = offaw + (size_t)(b * NQ + q) * 384;
    // lane-distributed loads (2 LDG per thread total)
    float offv  = rowp[hh * 32 + lane];                 // offsets 0..31
    float awraw = rowp[256 + hh * 16 + c2];             // both halves load same 16

    // softmax over the 16 aw values (within each 16-lane group; groups identical)
    float mx = awraw;
    #pragma unroll
    for (int o = 8; o > 0; o >>= 1) mx = fmaxf(mx, __shfl_xor_sync(FULL, mx, o, 16));
    float e = __expf(awraw - mx);
    float ssum = e;
    #pragma unroll
    for (int o = 8; o > 0; o >>= 1) ssum += __shfl_xor_sync(FULL, ssum, o, 16);
    float myaw = e / ssum;   // lane holds normalized aw[c2]

    float accx = 0.f, accy = 0.f;
    #pragma unroll
    for (int l = 0; l < NL; l++) {
        int w = LVL_SIZE[l];
        int startl = LVL_START[l];
        const __half* vbase = val + ((size_t)b * NQ + startl) * DIM + hh * HD + 2 * c2;
        float inv = 1.0f / (float)w;
        #pragma unroll
        for (int pp = 0; pp < 2; pp++) {
            int j = l * NP + pp * 2 + ph;               // this half's point index
            float ox = __shfl_sync(FULL, offv, 2 * j);
            float oy = __shfl_sync(FULL, offv, 2 * j + 1);
            float a  = __shfl_sync(FULL, myaw, j);      // j < 16 -> lane j
            float sx = (refx + ox * inv) * w - 0.5f;
            float sy = (refy + oy * inv) * w - 0.5f;
            int x0 = (int)floorf(sx);
            int y0 = (int)floorf(sy);
            float lx = sx - (float)x0;
            float ly = sy - (float)y0;
            float wts[4] = { (1.f - lx) * (1.f - ly), lx * (1.f - ly),
                             (1.f - lx) * ly,         lx * ly };
            float gx = 0.f, gy = 0.f;
            #pragma unroll
            for (int cor = 0; cor < 4; cor++) {
                int xi = x0 + (cor & 1);
                int yi = y0 + (cor >> 1);
                float m = (xi >= 0 && xi < w && yi >= 0 && yi < w) ? wts[cor] : 0.f;
                int cx = min(max(xi, 0), w - 1);
                int cy = min(max(yi, 0), w - 1);
                __half2 hv = *(const __half2*)(vbase + (size_t)(cy * w + cx) * DIM);
                float2 fv = __half22float2(hv);
                gx = fmaf(m, fv.x, gx);
                gy = fmaf(m, fv.y, gy);
            }
            accx = fmaf(a, gx, accx);
            accy = fmaf(a, gy, accy);
        }
    }
    // combine the two point-parity halves
    accx += __shfl_down_sync(FULL, accx, 16);
    accy += __shfl_down_sync(FULL, accy, 16);
    if (ph == 0) {
        *(__half2*)(samp + (size_t)(b * NQ + q) * DIM + hh * HD + 2 * c2) =
            __floats2half2_rn(accx, accy);
    }
}

// ---------------- depthwise 3x3 + bias + GELU (HALF in, half out) -------------
__global__ void __launch_bounds__(256)
dwconv_gelu_tiled(const __half* __restrict__ h1, const float* __restrict__ Wdw,
                  const float* __restrict__ bdw, __half* __restrict__ h2) {
    extern __shared__ float ts[];   // [100][128]
    int tile = blockIdx.x;
    int c0 = blockIdx.y * 128;
    int b = blockIdx.z;
    int l, tx, ty;
    if      (tile < 64) { l = 0; ty = tile >> 3; tx = tile & 7; }
    else if (tile < 80) { int u = tile - 64; l = 1; ty = u >> 2; tx = u & 3; }
    else if (tile < 84) { int u = tile - 80; l = 2; ty = u >> 1; tx = u & 1; }
    else                { l = 3; ty = 0; tx = 0; }
    int w = LVL_SIZE[l];
    int start = LVL_START[l];
    int t = threadIdx.x;
    int c = t & 127;
    int half = t >> 7;

    const __half* hbase = h1 + ((size_t)b * NQ + start) * HID + c0 + c;
    for (int p = half; p < 100; p += 2) {
        int py = p / 10 - 1 + ty * 8;
        int px = p % 10 - 1 + tx * 8;
        float v = 0.f;
        if (py >= 0 && py < w && px >= 0 && px < w)
            v = __half2float(hbase[(size_t)(py * w + px) * HID]);
        ts[p * 128 + c] = v;
    }
    float w9[9];
    #pragma unroll
    for (int j = 0; j < 9; j++) w9[j] = Wdw[j * HID + c0 + c];
    float bs = bdw[c0 + c];
    __syncthreads();

    __half* obase = h2 + ((size_t)b * NQ + start + (ty * 8) * w + tx * 8) * HID + c0 + c;
    for (int p = half; p < 64; p += 2) {
        int py = p >> 3, px = p & 7;
        float acc = bs;
        #pragma unroll
        for (int ky = 0; ky < 3; ky++)
            #pragma unroll
            for (int kx = 0; kx < 3; kx++)
                acc = fmaf(ts[((py + ky) * 10 + px + kx) * 128 + c], w9[ky * 3 + kx], acc);
        float gelu = acc * 0.5f * (1.0f + erff(acc * 0.70710678118654752440f));
        obase[(size_t)(py * w + px) * HID] = __float2half_rn(gelu);
    }
}
#define DW_SMEM_BYTES (100u * 128u * 4u)   // 51200

// ---------------- launch ----------------
extern "C" void kernel_launch(void* const* d_in, const int* in_sizes, int n_in,
                              void* d_out, int out_size) {
    const float* q0 = (const float*)d_in[0];
    const float* v0 = (const float*)d_in[1];
    const float* q1 = (const float*)d_in[2];
    const float* v1 = (const float*)d_in[3];
    const float* q2 = (const float*)d_in[4];
    const float* v2 = (const float*)d_in[5];
    const float* q3 = (const float*)d_in[6];
    const float* v3 = (const float*)d_in[7];
    const float* vn_g  = (const float*)d_in[8];
    const float* vn_b  = (const float*)d_in[9];
    const float* W_off = (const float*)d_in[10];
    const float* b_off = (const float*)d_in[11];
    const float* W_attn= (const float*)d_in[12];
    const float* b_attn= (const float*)d_in[13];
    const float* W_val = (const float*)d_in[14];
    const float* b_val = (const float*)d_in[15];
    const float* W_out = (const float*)d_in[16];
    const float* b_out = (const float*)d_in[17];
    const float* W_fc1 = (const float*)d_in[18];
    const float* b_fc1 = (const float*)d_in[19];
    const float* W_dw  = (const float*)d_in[20];
    const float* b_dw  = (const float*)d_in[21];
    const float* W_fc2 = (const float*)d_in[22];
    const float* b_fc2 = (const float*)d_in[23];
    float* out = (float*)d_out;

    __half *gqh, *gvnh, *gvalh, *gsamph, *gxh, *gh1h, *gh2h;
    __half *wtval, *wtoffaw, *wtout, *wtfc1, *wtfc2;
    float *gq32, *gv, *goffaw, *gx, *boffaw;
    cudaGetSymbolAddress((void**)&gqh,    g_qh);
    cudaGetSymbolAddress((void**)&gq32,   g_q32);
    cudaGetSymbolAddress((void**)&gv,     g_value);
    cudaGetSymbolAddress((void**)&gvnh,   g_vnh);
    cudaGetSymbolAddress((void**)&gvalh,  g_valh);
    cudaGetSymbolAddress((void**)&goffaw, g_offaw);
    cudaGetSymbolAddress((void**)&gsamph, g_samph);
    cudaGetSymbolAddress((void**)&gx,     g_x);
    cudaGetSymbolAddress((void**)&gxh,    g_xh);
    cudaGetSymbolAddress((void**)&gh1h,   g_h1h);
    cudaGetSymbolAddress((void**)&gh2h,   g_h2h);
    cudaGetSymbolAddress((void**)&wtval,  g_WT_val);
    cudaGetSymbolAddress((void**)&wtoffaw,g_WT_offaw);
    cudaGetSymbolAddress((void**)&boffaw, g_b_offaw);
    cudaGetSymbolAddress((void**)&wtout,  g_WT_out);
    cudaGetSymbolAddress((void**)&wtfc1,  g_WT_fc1);
    cudaGetSymbolAddress((void**)&wtfc2,  g_WT_fc2);

    cudaFuncSetAttribute(hgemm256_kernel,
                         cudaFuncAttributeMaxDynamicSharedMemorySize, SM256_BYTES);
    cudaFuncSetAttribute(hgemm_kernel,
                         cudaFuncAttributeMaxDynamicSharedMemorySize, GEMM_SMEM_BYTES);
    cudaFuncSetAttribute(dwconv_gelu_tiled,
                         cudaFuncAttributeMaxDynamicSharedMemorySize, DW_SMEM_BYTES);

    transpose_all_kernel<<<737, 256>>>(W_val, W_off, W_attn, W_out, W_fc1, W_fc2,
                                       b_off, b_attn,
                                       wtval, wtoffaw, wtout, wtfc1, wtfc2, boffaw);

    flatten_all_kernel<<<2720, 256>>>(q0, v0, q1, v1, q2, v2, q3, v3, gqh, gq32, gv);

    layernorm_kernel<<<MROWS, 256>>>(gv, vn_g, vn_b, gvnh);

    const int MT = MROWS / 128;  // 85
    // val (HALF only) = LN(value) @ W_val + b_val
    hgemm256_kernel<<<dim3(DIM / 64, MT), 256, SM256_BYTES>>>(gvnh, wtval, b_val, nullptr,
                                                              nullptr, gvalh, DIM);
    // [off | aw_raw] = query @ [W_off | W_attn] + [b_off | b_attn]
    hgemm256_kernel<<<dim3(384 / 64, MT), 256, SM256_BYTES>>>(gqh, wtoffaw, boffaw, nullptr,
                                                              goffaw, nullptr, 384);

    // sampling (softmax fused), half val in, half samp out
    deform_kernel<<<(MROWS * NH * 32 + 255) / 256, 256>>>(gvalh, goffaw, gsamph);

    // x = query + samp @ W_out + b_out   (fp32 + half outputs)
    hgemm256_kernel<<<dim3(DIM / 64, MT), 256, SM256_BYTES>>>(gsamph, wtout, b_out, gq32,
                                                              gx, gxh, DIM);
    // h1 (HALF only) = x @ W_fc1 + b_fc1
    hgemm256_kernel<<<dim3(HID / 64, MT), 256, SM256_BYTES>>>(gxh, wtfc1, b_fc1, nullptr,
                                                              nullptr, gh1h, HID);

    // h2 = gelu(dwconv(h1) + b_dw), half in/out
    dwconv_gelu_tiled<<<dim3(85, 8, BB), 256, DW_SMEM_BYTES>>>(gh1h, W_dw, b_dw, gh2h);

    // out = x + h2 @ W_fc2 + b_fc2  (K=1024, chunked pipeline)
    hgemm_kernel<<<dim3(DIM / 64, MT), 256, GEMM_SMEM_BYTES>>>(gh2h, wtfc2, b_fc2, gx,
                                                               out, nullptr, DIM, HID);
}

// round 16
// speedup vs baseline: 1.3364x; 1.2091x over previous
#include <cuda_runtime.h>
#include <cuda_fp16.h>
#include <math.h>
#include <stdint.h>

// ---------------- problem constants ----------------
#define BB   2
#define DIM  256
#define NH   8
#define HD   32
#define NL   4
#define NP   4
#define HID  1024
#define NQ   5440
#define MROWS (BB*NQ)   // 10880 = 85*128

__device__ __constant__ int LVL_SIZE[4]  = {64, 32, 16, 8};
__device__ __constant__ int LVL_START[4] = {0, 4096, 5120, 5376};

// ---------------- scratch ----------------
__device__ __half g_qh   [(size_t)MROWS * DIM];
__device__ float  g_q32  [(size_t)MROWS * DIM];
__device__ float  g_value[(size_t)MROWS * DIM];
__device__ __half g_vnh  [(size_t)MROWS * DIM];
__device__ __half g_valh [(size_t)MROWS * DIM];
__device__ float  g_offaw[(size_t)MROWS * 384];
__device__ __half g_samph[(size_t)MROWS * DIM];
__device__ float  g_x    [(size_t)MROWS * DIM];
__device__ __half g_xh   [(size_t)MROWS * DIM];
__device__ __half g_h1h  [(size_t)MROWS * HID];
__device__ __half g_h2h  [(size_t)MROWS * HID];
// transposed weights [N, K] in half
__device__ __half g_WT_val  [DIM * DIM];
__device__ __half g_WT_offaw[384 * DIM];
__device__ float  g_b_offaw [384];
__device__ __half g_WT_out  [DIM * DIM];
__device__ __half g_WT_fc1  [HID * DIM];
__device__ __half g_WT_fc2  [DIM * HID];

// ---------------- cp.async helpers ----------------
__device__ __forceinline__ void cp_async16(uint32_t smem, const void* gmem) {
    asm volatile("cp.async.cg.shared.global [%0], [%1], 16;" :: "r"(smem), "l"(gmem));
}
#define CP_COMMIT() asm volatile("cp.async.commit_group;")
#define CP_WAIT0()  asm volatile("cp.async.wait_group 0;")
#define CP_WAIT1()  asm volatile("cp.async.wait_group 1;")

// ---------------- mma.sync m16n8k16 f16 (fp32 accum) ----------------
__device__ __forceinline__ void mma_f16(float* d, const uint32_t* a, const uint32_t* b) {
    asm volatile(
        "mma.sync.aligned.m16n8k16.row.col.f32.f16.f16.f32 "
        "{%0,%1,%2,%3}, {%4,%5,%6,%7}, {%8,%9}, {%0,%1,%2,%3};\n"
        : "+f"(d[0]), "+f"(d[1]), "+f"(d[2]), "+f"(d[3])
        : "r"(a[0]), "r"(a[1]), "r"(a[2]), "r"(a[3]), "r"(b[0]), "r"(b[1]));
}

// ================= ONE-SHOT K=256 GEMM body (128x64 tile) =====================
#define LDL 264
#define SM256_BYTES ((128 + 64) * LDL * 2)   // 101376 B

__device__ __forceinline__ void
hgemm256_body(const __half* __restrict__ A, const __half* __restrict__ WT,
              const float* __restrict__ bias, const float* __restrict__ resid,
              float* __restrict__ C, __half* __restrict__ Ch, int N,
              int row0, int col0, __half* hsm) {
    __half* Bsmem = hsm + 128 * LDL;
    const int t = threadIdx.x;
    const int lane = t & 31;
    const int wid  = t >> 5;
    const int wm = (wid & 3) * 32;
    const int wn = (wid >> 2) * 32;
    const int g   = lane >> 2;
    const int tig = lane & 3;

    const uint32_t as_u = (uint32_t)__cvta_generic_to_shared(hsm);
    const uint32_t bs_u = (uint32_t)__cvta_generic_to_shared(Bsmem);

    #pragma unroll
    for (int j = 0; j < 16; j++) {
        int slot = t + 256 * j;
        int r = slot >> 5, seg = slot & 31;
        cp_async16(as_u + (uint32_t)((r * LDL + seg * 8) * 2),
                   A + (size_t)(row0 + r) * 256 + seg * 8);
    }
    #pragma unroll
    for (int j = 0; j < 8; j++) {
        int slot = t + 256 * j;
        int r = slot >> 5, seg = slot & 31;
        cp_async16(bs_u + (uint32_t)((r * LDL + seg * 8) * 2),
                   WT + (size_t)(col0 + r) * 256 + seg * 8);
    }
    CP_COMMIT();

    float acc[2][4][4];
    #pragma unroll
    for (int i = 0; i < 2; i++)
        #pragma unroll
        for (int j = 0; j < 4; j++)
            #pragma unroll
            for (int r = 0; r < 4; r++) acc[i][j][r] = 0.f;

    CP_WAIT0();
    __syncthreads();

    #pragma unroll
    for (int ks = 0; ks < 16; ks++) {
        const int k0h = ks * 16;
        uint32_t bfr[4][2];
        #pragma unroll
        for (int nt = 0; nt < 4; nt++) {
            const __half* p = Bsmem + (wn + nt * 8 + g) * LDL + k0h + 2 * tig;
            bfr[nt][0] = *(const uint32_t*)(p);
            bfr[nt][1] = *(const uint32_t*)(p + 8);
        }
        #pragma unroll
        for (int mt = 0; mt < 2; mt++) {
            const __half* p = hsm + (wm + mt * 16 + g) * LDL + k0h + 2 * tig;
            uint32_t afr[4];
            afr[0] = *(const uint32_t*)(p);
            afr[1] = *(const uint32_t*)(p + 8 * LDL);
            afr[2] = *(const uint32_t*)(p + 8);
            afr[3] = *(const uint32_t*)(p + 8 * LDL + 8);
            #pragma unroll
            for (int nt = 0; nt < 4; nt++) mma_f16(acc[mt][nt], afr, bfr[nt]);
        }
    }

    #pragma unroll
    for (int mt = 0; mt < 2; mt++) {
        int r0 = row0 + wm + mt * 16 + g;
        #pragma unroll
        for (int nt = 0; nt < 4; nt++) {
            int cc = col0 + wn + nt * 8 + tig * 2;
            float2 bv = *(const float2*)(bias + cc);
            float2 v0, v1;
            v0.x = acc[mt][nt][0] + bv.x;
            v0.y = acc[mt][nt][1] + bv.y;
            v1.x = acc[mt][nt][2] + bv.x;
            v1.y = acc[mt][nt][3] + bv.y;
            if (resid) {
                float2 ra = *(const float2*)(resid + (size_t)r0 * N + cc);
                float2 rb = *(const float2*)(resid + (size_t)(r0 + 8) * N + cc);
                v0.x += ra.x; v0.y += ra.y;
                v1.x += rb.x; v1.y += rb.y;
            }
            if (C) {
                *(float2*)(C + (size_t)r0 * N + cc)       = v0;
                *(float2*)(C + (size_t)(r0 + 8) * N + cc) = v1;
            }
            if (Ch) {
                *(__half2*)(Ch + (size_t)r0 * N + cc)       = __floats2half2_rn(v0.x, v0.y);
                *(__half2*)(Ch + (size_t)(r0 + 8) * N + cc) = __floats2half2_rn(v1.x, v1.y);
            }
        }
    }
}

__global__ void __launch_bounds__(256)
hgemm256_kernel(const __half* __restrict__ A, const __half* __restrict__ WT,
                const float* __restrict__ bias, const float* __restrict__ resid,
                float* __restrict__ C, __half* __restrict__ Ch, int N) {
    extern __shared__ __half hsm[];
    hgemm256_body(A, WT, bias, resid, C, Ch, N, blockIdx.y * 128, blockIdx.x * 64, hsm);
}

// dual launch: bx<4 -> val GEMM (half out), bx>=4 -> offaw GEMM (fp32 out)
__global__ void __launch_bounds__(256)
hgemm256_dual_kernel(const __half* __restrict__ Aval, const __half* __restrict__ WTval,
                     const float* __restrict__ bval, __half* __restrict__ Cvalh,
                     const __half* __restrict__ Aoff, const __half* __restrict__ WToff,
                     const float* __restrict__ boff, float* __restrict__ Coff) {
    extern __shared__ __half hsm[];
    int bx = blockIdx.x;
    if (bx < 4) {
        hgemm256_body(Aval, WTval, bval, nullptr, nullptr, Cvalh, 256,
                      blockIdx.y * 128, bx * 64, hsm);
    } else {
        hgemm256_body(Aoff, WToff, boff, nullptr, Coff, nullptr, 384,
                      blockIdx.y * 128, (bx - 4) * 64, hsm);
    }
}

// ================= chunked 3-stage GEMM (for K=1024 fc2) =======================
#define LDH 40
#define STG 3
#define STAGE_A (128 * LDH)
#define STAGE_B (64 * LDH)

__global__ void __launch_bounds__(256)
hgemm_kernel(const __half* __restrict__ A, const __half* __restrict__ WT,
             const float* __restrict__ bias, const float* __restrict__ resid,
             float* __restrict__ C, __half* __restrict__ Ch, int N, int K) {
    extern __shared__ __half hsm[];
    __half* Bsmem = hsm + STG * STAGE_A;

    const int t = threadIdx.x;
    const int lane = t & 31;
    const int wid  = t >> 5;
    const int wm = (wid & 3) * 32;
    const int wn = (wid >> 2) * 32;
    const int g   = lane >> 2;
    const int tig = lane & 3;
    const int row0 = blockIdx.y * 128;
    const int col0 = blockIdx.x * 64;

    const uint32_t as_u = (uint32_t)__cvta_generic_to_shared(hsm);
    const uint32_t bs_u = (uint32_t)__cvta_generic_to_shared(Bsmem);

    float acc[2][4][4];
    #pragma unroll
    for (int i = 0; i < 2; i++)
        #pragma unroll
        for (int j = 0; j < 4; j++)
            #pragma unroll
            for (int r = 0; r < 4; r++) acc[i][j][r] = 0.f;

    const int NC = K >> 5;

    #pragma unroll
    for (int pc = 0; pc < 2; pc++) {
        const int k0 = pc << 5;
        const int soA = pc * STAGE_A;
        #pragma unroll
        for (int j = 0; j < 2; j++) {
            int slot = t + 256 * j;
            int r = slot >> 2, seg = slot & 3;
            cp_async16(as_u + (uint32_t)((soA + r * LDH + seg * 8) * 2),
                       A + (size_t)(row0 + r) * K + k0 + seg * 8);
        }
        const int soB = pc * STAGE_B;
        int r = t >> 2, seg = t & 3;
        cp_async16(bs_u + (uint32_t)((soB + r * LDH + seg * 8) * 2),
                   WT + (size_t)(col0 + r) * K + k0 + seg * 8);
        CP_COMMIT();
    }

    int stage = 0, pstage = 2;
    for (int c = 0; c < NC; c++) {
        if (c == NC - 1) { CP_WAIT0(); } else { CP_WAIT1(); }
        __syncthreads();
        if (c + 2 < NC) {
            const int k0 = (c + 2) << 5;
            const int soA = pstage * STAGE_A;
            #pragma unroll
            for (int j = 0; j < 2; j++) {
                int slot = t + 256 * j;
                int r = slot >> 2, seg = slot & 3;
                cp_async16(as_u + (uint32_t)((soA + r * LDH + seg * 8) * 2),
                           A + (size_t)(row0 + r) * K + k0 + seg * 8);
            }
            const int soB = pstage * STAGE_B;
            int r = t >> 2, seg = t & 3;
            cp_async16(bs_u + (uint32_t)((soB + r * LDH + seg * 8) * 2),
                       WT + (size_t)(col0 + r) * K + k0 + seg * 8);
            CP_COMMIT();
        }
        const __half* Asb = hsm   + stage * STAGE_A;
        const __half* Bsb = Bsmem + stage * STAGE_B;
        #pragma unroll
        for (int ks = 0; ks < 2; ks++) {
            const int k0h = ks * 16;
            uint32_t bfr[4][2];
            #pragma unroll
            for (int nt = 0; nt < 4; nt++) {
                const __half* p = Bsb + (wn + nt * 8 + g) * LDH + k0h + 2 * tig;
                bfr[nt][0] = *(const uint32_t*)(p);
                bfr[nt][1] = *(const uint32_t*)(p + 8);
            }
            #pragma unroll
            for (int mt = 0; mt < 2; mt++) {
                const __half* p = Asb + (wm + mt * 16 + g) * LDH + k0h + 2 * tig;
                uint32_t afr[4];
                afr[0] = *(const uint32_t*)(p);
                afr[1] = *(const uint32_t*)(p + 8 * LDH);
                afr[2] = *(const uint32_t*)(p + 8);
                afr[3] = *(const uint32_t*)(p + 8 * LDH + 8);
                #pragma unroll
                for (int nt = 0; nt < 4; nt++) mma_f16(acc[mt][nt], afr, bfr[nt]);
            }
        }
        stage = (stage == STG - 1) ? 0 : stage + 1;
        pstage = (pstage == STG - 1) ? 0 : pstage + 1;
    }
    __syncthreads();

    #pragma unroll
    for (int mt = 0; mt < 2; mt++) {
        int r0 = row0 + wm + mt * 16 + g;
        #pragma unroll
        for (int nt = 0; nt < 4; nt++) {
            int cc = col0 + wn + nt * 8 + tig * 2;
            float2 bv = *(const float2*)(bias + cc);
            float2 v0, v1;
            v0.x = acc[mt][nt][0] + bv.x;
            v0.y = acc[mt][nt][1] + bv.y;
            v1.x = acc[mt][nt][2] + bv.x;
            v1.y = acc[mt][nt][3] + bv.y;
            if (resid) {
                float2 ra = *(const float2*)(resid + (size_t)r0 * N + cc);
                float2 rb = *(const float2*)(resid + (size_t)(r0 + 8) * N + cc);
                v0.x += ra.x; v0.y += ra.y;
                v1.x += rb.x; v1.y += rb.y;
            }
            if (C) {
                *(float2*)(C + (size_t)r0 * N + cc)       = v0;
                *(float2*)(C + (size_t)(r0 + 8) * N + cc) = v1;
            }
            if (Ch) {
                *(__half2*)(Ch + (size_t)r0 * N + cc)       = __floats2half2_rn(v0.x, v0.y);
                *(__half2*)(Ch + (size_t)(r0 + 8) * N + cc) = __floats2half2_rn(v1.x, v1.y);
            }
        }
    }
}

#define GEMM_SMEM_BYTES ((unsigned)(STG * (STAGE_A + STAGE_B) * 2))   // 46080 B

// ======= merged prologue: weight transposes + bias concat + q/v flatten =======
// blocks [0,736]: transpose tiles + bias; blocks [737, 737+2720): flatten tiles
__global__ void __launch_bounds__(256)
prologue_kernel(const float* __restrict__ s_val, const float* __restrict__ s_off,
                const float* __restrict__ s_attn, const float* __restrict__ s_out,
                const float* __restrict__ s_fc1, const float* __restrict__ s_fc2,
                const float* __restrict__ b_off, const float* __restrict__ b_attn,
                __half* __restrict__ d_val, __half* __restrict__ d_offaw,
                __half* __restrict__ d_out, __half* __restrict__ d_fc1,
                __half* __restrict__ d_fc2, float* __restrict__ d_b_offaw,
                const float* __restrict__ q0, const float* __restrict__ v0,
                const float* __restrict__ q1, const float* __restrict__ v1,
                const float* __restrict__ q2, const float* __restrict__ v2,
                const float* __restrict__ q3, const float* __restrict__ v3,
                __half* __restrict__ gqh, float* __restrict__ gq32,
                float* __restrict__ gv) {
    __shared__ float pool[2 * 32 * 33];
    int blk = blockIdx.x;
    int t = threadIdx.x;
    if (blk < 737) {
        int u = blk;
        if (u == 736) {
            if (t < 128) {
                d_b_offaw[t]       = b_off[t];
                d_b_offaw[t + 128] = b_off[t + 128];
            } else {
                int j = t - 128;
                d_b_offaw[256 + j] = b_attn[j];
            }
            return;
        }
        const float* src; __half* dst; int K, N;
        if      (u < 64)  {            src = s_val;  dst = d_val;             K = 256;  N = 256; }
        else if (u < 128) { u -= 64;   src = s_off;  dst = d_offaw;           K = 256;  N = 256; }
        else if (u < 160) { u -= 128;  src = s_attn; dst = d_offaw + 256*256; K = 256;  N = 128; }
        else if (u < 224) { u -= 160;  src = s_out;  dst = d_out;             K = 256;  N = 256; }
        else if (u < 480) { u -= 224;  src = s_fc1;  dst = d_fc1;             K = 256;  N = 1024; }
        else              { u -= 480;  src = s_fc2;  dst = d_fc2;             K = 1024; N = 256; }
        int nt = N >> 5;
        int by = (u / nt) * 32, bx = (u % nt) * 32;
        float (*tile)[33] = (float(*)[33])pool;
        int tx = t & 31, ty = t >> 5;
        #pragma unroll
        for (int i = 0; i < 32; i += 8)
            tile[ty + i][tx] = src[(size_t)(by + ty + i) * N + bx + tx];
        __syncthreads();
        #pragma unroll
        for (int i = 0; i < 32; i += 8)
            dst[(size_t)(bx + ty + i) * K + by + tx] = __float2half_rn(tile[tx][ty + i]);
    } else {
        int fb = blk - 737;
        int b = fb / 1360;
        int u = fb % 1360;
        const float *qs, *vs; int n, start;
        if      (u < 1024) {            qs = q0; vs = v0; n = 4096; start = 0; }
        else if (u < 1280) { u -= 1024; qs = q1; vs = v1; n = 1024; start = 4096; }
        else if (u < 1344) { u -= 1280; qs = q2; vs = v2; n = 256;  start = 5120; }
        else               { u -= 1344; qs = q3; vs = v3; n = 64;   start = 5376; }
        int pt = n >> 5;
        int ct = u / pt;
        int pi = u % pt;
        float (*tq)[33] = (float(*)[33])pool;
        float (*tv)[33] = (float(*)[33])(pool + 32 * 33);
        int tx = t & 31, ty = t >> 5;
        const float* qb = qs + (size_t)(b * DIM + ct * 32) * n + pi * 32;
        const float* vb = vs + (size_t)(b * DIM + ct * 32) * n + pi * 32;
        #pragma unroll
        for (int i = 0; i < 32; i += 8) {
            tq[ty + i][tx] = qb[(size_t)(ty + i) * n + tx];
            tv[ty + i][tx] = vb[(size_t)(ty + i) * n + tx];
        }
        __syncthreads();
        size_t obase = ((size_t)b * NQ + start + pi * 32) * DIM + ct * 32;
        #pragma unroll
        for (int i = 0; i < 32; i += 8) {
            float qv = tq[tx][ty + i];
            gq32[obase + (size_t)(ty + i) * DIM + tx] = qv;
            gqh [obase + (size_t)(ty + i) * DIM + tx] = __float2half_rn(qv);
            gv  [obase + (size_t)(ty + i) * DIM + tx] = tv[tx][ty + i];
        }
    }
}

// ---------------- layernorm (fp32 in, half out) ----------------
__global__ void layernorm_kernel(const float* __restrict__ x, const float* __restrict__ g,
                                 const float* __restrict__ bia, __half* __restrict__ out) {
    int row = blockIdx.x;
    int t = threadIdx.x;
    float v = x[(size_t)row * DIM + t];
    __shared__ float sm[40];
    float s = v;
    #pragma unroll
    for (int o = 16; o > 0; o >>= 1) s += __shfl_xor_sync(0xffffffffu, s, o);
    if ((t & 31) == 0) sm[t >> 5] = s;
    __syncthreads();
    if (t < 8) {
        float z = sm[t];
        #pragma unroll
        for (int o = 4; o > 0; o >>= 1) z += __shfl_xor_sync(0xffu, z, o);
        if (t == 0) sm[32] = z;
    }
    __syncthreads();
    float mean = sm[32] * (1.0f / DIM);
    float d = v - mean;
    float s2 = d * d;
    #pragma unroll
    for (int o = 16; o > 0; o >>= 1) s2 += __shfl_xor_sync(0xffffffffu, s2, o);
    if ((t & 31) == 0) sm[8 + (t >> 5)] = s2;
    __syncthreads();
    if (t < 8) {
        float z = sm[8 + t];
        #pragma unroll
        for (int o = 4; o > 0; o >>= 1) z += __shfl_xor_sync(0xffu, z, o);
        if (t == 0) sm[33] = z;
    }
    __syncthreads();
    float var = sm[33] * (1.0f / DIM);
    out[(size_t)row * DIM + t] = __float2half_rn(d * rsqrtf(var + 1e-5f) * g[t] + bia[t]);
}

// ---------------- deformable sampling v3: half4 gathers, 4-point parallel -----
// warp = (b, q, head). Quarter-warp ph=lane>>3 owns sample point ph of each
// level; c4=lane&7 covers the head's 32 channels as 8 half4 (8B) loads.
__global__ void __launch_bounds__(256)
deform_kernel(const __half* __restrict__ val, const float* __restrict__ offaw,
              __half* __restrict__ samp) {
    const unsigned FULL = 0xffffffffu;
    int gw = (blockIdx.x * blockDim.x + threadIdx.x) >> 5;
    int lane = threadIdx.x & 31;
    if (gw >= MROWS * NH) return;
    int hh = gw % NH;
    int q  = (gw / NH) % NQ;
    int b  = gw / (NH * NQ);
    int ph = lane >> 3;      // point index within level (0..3)
    int c4 = lane & 7;       // half4 channel group

    int lqv, local;
    if (q < 4096)      { lqv = 0; local = q; }
    else if (q < 5120) { lqv = 1; local = q - 4096; }
    else if (q < 5376) { lqv = 2; local = q - 5120; }
    else               { lqv = 3; local = q - 5376; }
    int szq = LVL_SIZE[lqv];
    float refx = ((local % szq) + 0.5f) / szq;
    float refy = ((local / szq) + 0.5f) / szq;

    const float* rowp = offaw + (size_t)(b * NQ + q) * 384;
    float offv  = rowp[hh * 32 + lane];
    float awraw = rowp[256 + hh * 16 + (lane & 15)];

    // softmax over 16 (per 16-lane group; both groups identical)
    float mx = awraw;
    #pragma unroll
    for (int o = 8; o > 0; o >>= 1) mx = fmaxf(mx, __shfl_xor_sync(FULL, mx, o, 16));
    float e = __expf(awraw - mx);
    float ssum = e;
    #pragma unroll
    for (int o = 8; o > 0; o >>= 1) ssum += __shfl_xor_sync(FULL, ssum, o, 16);
    float myaw = e / ssum;

    float acc0 = 0.f, acc1 = 0.f, acc2 = 0.f, acc3 = 0.f;
    #pragma unroll
    for (int l = 0; l < NL; l++) {
        int w = LVL_SIZE[l];
        int startl = LVL_START[l];
        const __half* vbase = val + ((size_t)b * NQ + startl) * DIM + hh * HD + 4 * c4;
        float inv = 1.0f / (float)w;
        int j = l * NP + ph;                       // 0..15
        float ox = __shfl_sync(FULL, offv, 2 * j);
        float oy = __shfl_sync(FULL, offv, 2 * j + 1);
        float a  = __shfl_sync(FULL, myaw, j);
        float sx = (refx + ox * inv) * w - 0.5f;
        float sy = (refy + oy * inv) * w - 0.5f;
        int x0 = (int)floorf(sx);
        int y0 = (int)floorf(sy);
        float lx = sx - (float)x0;
        float ly = sy - (float)y0;
        float wts[4] = { (1.f - lx) * (1.f - ly), lx * (1.f - ly),
                         (1.f - lx) * ly,         lx * ly };
        #pragma unroll
        for (int cor = 0; cor < 4; cor++) {
            int xi = x0 + (cor & 1);
            int yi = y0 + (cor >> 1);
            float m = (xi >= 0 && xi < w && yi >= 0 && yi < w) ? a * wts[cor] : 0.f;
            int cx = min(max(xi, 0), w - 1);
            int cy = min(max(yi, 0), w - 1);
            uint2 hv = *(const uint2*)(vbase + (size_t)(cy * w + cx) * DIM);
            float2 f01 = __half22float2(*reinterpret_cast<__half2*>(&hv.x));
            float2 f23 = __half22float2(*reinterpret_cast<__half2*>(&hv.y));
            acc0 = fmaf(m, f01.x, acc0);
            acc1 = fmaf(m, f01.y, acc1);
            acc2 = fmaf(m, f23.x, acc2);
            acc3 = fmaf(m, f23.y, acc3);
        }
    }
    // reduce the 4 point-quarters: lanes 0..7 end with totals
    acc0 += __shfl_down_sync(FULL, acc0, 16);
    acc1 += __shfl_down_sync(FULL, acc1, 16);
    acc2 += __shfl_down_sync(FULL, acc2, 16);
    acc3 += __shfl_down_sync(FULL, acc3, 16);
    acc0 += __shfl_down_sync(FULL, acc0, 8);
    acc1 += __shfl_down_sync(FULL, acc1, 8);
    acc2 += __shfl_down_sync(FULL, acc2, 8);
    acc3 += __shfl_down_sync(FULL, acc3, 8);
    if (lane < 8) {
        __half2 a01 = __floats2half2_rn(acc0, acc1);
        __half2 a23 = __floats2half2_rn(acc2, acc3);
        uint2 u;
        u.x = *reinterpret_cast<uint32_t*>(&a01);
        u.y = *reinterpret_cast<uint32_t*>(&a23);
        *(uint2*)(samp + (size_t)(b * NQ + q) * DIM + hh * HD + 4 * c4) = u;
    }
}

// ---------------- depthwise 3x3 + bias + GELU, half2-vectorized ---------------
// block: 128 channels (64 half2) x one spatial tile; thread = (c2 = t&63, grp = t>>6)
__global__ void __launch_bounds__(256)
dwconv_gelu_tiled(const __half* __restrict__ h1, const float* __restrict__ Wdw,
                  const float* __restrict__ bdw, __half* __restrict__ h2) {
    extern __shared__ float2 ts2[];   // [100][64]
    int tile = blockIdx.x;
    int c0 = blockIdx.y * 128;
    int b = blockIdx.z;
    int l, tx, ty;
    if      (tile < 64) { l = 0; ty = tile >> 3; tx = tile & 7; }
    else if (tile < 80) { int u = tile - 64; l = 1; ty = u >> 2; tx = u & 3; }
    else if (tile < 84) { int u = tile - 80; l = 2; ty = u >> 1; tx = u & 1; }
    else                { l = 3; ty = 0; tx = 0; }
    int w = LVL_SIZE[l];
    int start = LVL_START[l];
    int t = threadIdx.x;
    int c2 = t & 63;         // half2 channel index (channels 2c2, 2c2+1)
    int grp = t >> 6;        // 0..3

    const __half* hbase = h1 + ((size_t)b * NQ + start) * HID + c0 + 2 * c2;
    for (int p = grp; p < 100; p += 4) {
        int py = p / 10 - 1 + ty * 8;
        int px = p % 10 - 1 + tx * 8;
        float2 v = make_float2(0.f, 0.f);
        if (py >= 0 && py < w && px >= 0 && px < w)
            v = __half22float2(*(const __half2*)(hbase + (size_t)(py * w + px) * HID));
        ts2[p * 64 + c2] = v;
    }
    float2 w9[9];
    #pragma unroll
    for (int j = 0; j < 9; j++) w9[j] = *(const float2*)(Wdw + j * HID + c0 + 2 * c2);
    float2 bs = *(const float2*)(bdw + c0 + 2 * c2);
    __syncthreads();

    __half* obase = h2 + ((size_t)b * NQ + start + (ty * 8) * w + tx * 8) * HID + c0 + 2 * c2;
    for (int p = grp; p < 64; p += 4) {
        int py = p >> 3, px = p & 7;
        float ax = bs.x, ay = bs.y;
        #pragma unroll
        for (int ky = 0; ky < 3; ky++)
            #pragma unroll
            for (int kx = 0; kx < 3; kx++) {
                float2 v = ts2[((py + ky) * 10 + px + kx) * 64 + c2];
                float2 ww = w9[ky * 3 + kx];
                ax = fmaf(v.x, ww.x, ax);
                ay = fmaf(v.y, ww.y, ay);
            }
        float gx = ax * 0.5f * (1.0f + erff(ax * 0.70710678118654752440f));
        float gy = ay * 0.5f * (1.0f + erff(ay * 0.70710678118654752440f));
        *(__half2*)(obase + (size_t)(py * w + px) * HID) = __floats2half2_rn(gx, gy);
    }
}
#define DW_SMEM_BYTES (100u * 64u * 8u)   // 51200

// ---------------- launch ----------------
extern "C" void kernel_launch(void* const* d_in, const int* in_sizes, int n_in,
                              void* d_out, int out_size) {
    const float* q0 = (const float*)d_in[0];
    const float* v0 = (const float*)d_in[1];
    const float* q1 = (const float*)d_in[2];
    const float* v1 = (const float*)d_in[3];
    const float* q2 = (const float*)d_in[4];
    const float* v2 = (const float*)d_in[5];
    const float* q3 = (const float*)d_in[6];
    const float* v3 = (const float*)d_in[7];
    const float* vn_g  = (const float*)d_in[8];
    const float* vn_b  = (const float*)d_in[9];
    const float* W_off = (const float*)d_in[10];
    const float* b_off = (const float*)d_in[11];
    const float* W_attn= (const float*)d_in[12];
    const float* b_attn= (const float*)d_in[13];
    const float* W_val = (const float*)d_in[14];
    const float* b_val = (const float*)d_in[15];
    const float* W_out = (const float*)d_in[16];
    const float* b_out = (const float*)d_in[17];
    const float* W_fc1 = (const float*)d_in[18];
    const float* b_fc1 = (const float*)d_in[19];
    const float* W_dw  = (const float*)d_in[20];
    const float* b_dw  = (const float*)d_in[21];
    const float* W_fc2 = (const float*)d_in[22];
    const float* b_fc2 = (const float*)d_in[23];
    float* out = (float*)d_out;

    __half *gqh, *gvnh, *gvalh, *gsamph, *gxh, *gh1h, *gh2h;
    __half *wtval, *wtoffaw, *wtout, *wtfc1, *wtfc2;
    float *gq32, *gv, *goffaw, *gx, *boffaw;
    cudaGetSymbolAddress((void**)&gqh,    g_qh);
    cudaGetSymbolAddress((void**)&gq32,   g_q32);
    cudaGetSymbolAddress((void**)&gv,     g_value);
    cudaGetSymbolAddress((void**)&gvnh,   g_vnh);
    cudaGetSymbolAddress((void**)&gvalh,  g_valh);
    cudaGetSymbolAddress((void**)&goffaw, g_offaw);
    cudaGetSymbolAddress((void**)&gsamph, g_samph);
    cudaGetSymbolAddress((void**)&gx,     g_x);
    cudaGetSymbolAddress((void**)&gxh,    g_xh);
    cudaGetSymbolAddress((void**)&gh1h,   g_h1h);
    cudaGetSymbolAddress((void**)&gh2h,   g_h2h);
    cudaGetSymbolAddress((void**)&wtval,  g_WT_val);
    cudaGetSymbolAddress((void**)&wtoffaw,g_WT_offaw);
    cudaGetSymbolAddress((void**)&boffaw, g_b_offaw);
    cudaGetSymbolAddress((void**)&wtout,  g_WT_out);
    cudaGetSymbolAddress((void**)&wtfc1,  g_WT_fc1);
    cudaGetSymbolAddress((void**)&wtfc2,  g_WT_fc2);

    cudaFuncSetAttribute(hgemm256_kernel,
                         cudaFuncAttributeMaxDynamicSharedMemorySize, SM256_BYTES);
    cudaFuncSetAttribute(hgemm256_dual_kernel,
                         cudaFuncAttributeMaxDynamicSharedMemorySize, SM256_BYTES);
    cudaFuncSetAttribute(hgemm_kernel,
                         cudaFuncAttributeMaxDynamicSharedMemorySize, GEMM_SMEM_BYTES);
    cudaFuncSetAttribute(dwconv_gelu_tiled,
                         cudaFuncAttributeMaxDynamicSharedMemorySize, DW_SMEM_BYTES);

    // prologue: weight transposes + flatten (merged)
    prologue_kernel<<<737 + 2720, 256>>>(W_val, W_off, W_attn, W_out, W_fc1, W_fc2,
                                         b_off, b_attn,
                                         wtval, wtoffaw, wtout, wtfc1, wtfc2, boffaw,
                                         q0, v0, q1, v1, q2, v2, q3, v3,
                                         gqh, gq32, gv);

    layernorm_kernel<<<MROWS, 256>>>(gv, vn_g, vn_b, gvnh);

    const int MT = MROWS / 128;  // 85
    // val (half) = LN(value) @ W_val + b_val  AND  [off|aw] = q @ [W_off|W_attn]
    hgemm256_dual_kernel<<<dim3(10, MT), 256, SM256_BYTES>>>(gvnh, wtval, b_val, gvalh,
                                                             gqh, wtoffaw, boffaw, goffaw);

    // sampling (softmax fused), half val in, half samp out
    deform_kernel<<<(MROWS * NH * 32 + 255) / 256, 256>>>(gvalh, goffaw, gsamph);

    // x = query + samp @ W_out + b_out   (fp32 + half outputs)
    hgemm256_kernel<<<dim3(DIM / 64, MT), 256, SM256_BYTES>>>(gsamph, wtout, b_out, gq32,
                                                              gx, gxh, DIM);
    // h1 (half) = x @ W_fc1 + b_fc1
    hgemm256_kernel<<<dim3(HID / 64, MT), 256, SM256_BYTES>>>(gxh, wtfc1, b_fc1, nullptr,
                                                              nullptr, gh1h, HID);

    // h2 = gelu(dwconv(h1) + b_dw)
    dwconv_gelu_tiled<<<dim3(85, 8, BB), 256, DW_SMEM_BYTES>>>(gh1h, W_dw, b_dw, gh2h);

    // out = x + h2 @ W_fc2 + b_fc2  (K=1024, chunked pipeline)
    hgemm_kernel<<<dim3(DIM / 64, MT), 256, GEMM_SMEM_BYTES>>>(gh2h, wtfc2, b_fc2, gx,
                                                               out, nullptr, DIM, HID);
}

// round 17
// speedup vs baseline: 1.4412x; 1.0784x over previous
#include <cuda_runtime.h>
#include <cuda_fp16.h>
#include <math.h>
#include <stdint.h>

// ---------------- problem constants ----------------
#define BB   2
#define DIM  256
#define NH   8
#define HD   32
#define NL   4
#define NP   4
#define HID  1024
#define NQ   5440
#define MROWS (BB*NQ)   // 10880 = 85*128

__device__ __constant__ int LVL_SIZE[4]  = {64, 32, 16, 8};
__device__ __constant__ int LVL_START[4] = {0, 4096, 5120, 5376};

// ---------------- scratch ----------------
__device__ __half g_qh   [(size_t)MROWS * DIM];
__device__ float  g_q32  [(size_t)MROWS * DIM];
__device__ float  g_value[(size_t)MROWS * DIM];
__device__ __half g_vnh  [(size_t)MROWS * DIM];
__device__ __half g_valh [(size_t)MROWS * DIM];
__device__ float  g_offaw[(size_t)MROWS * 384];
__device__ __half g_samph[(size_t)MROWS * DIM];
__device__ float  g_x    [(size_t)MROWS * DIM];
__device__ __half g_xh   [(size_t)MROWS * DIM];
__device__ __half g_h1h  [(size_t)MROWS * HID];
__device__ __half g_h2h  [(size_t)MROWS * HID];
// transposed weights [N, K] in half
__device__ __half g_WT_val  [DIM * DIM];
__device__ __half g_WT_offaw[384 * DIM];
__device__ float  g_b_offaw [384];
__device__ __half g_WT_out  [DIM * DIM];
__device__ __half g_WT_fc1  [HID * DIM];
__device__ __half g_WT_fc2  [DIM * HID];

// ---------------- cp.async helpers ----------------
__device__ __forceinline__ void cp_async16(uint32_t smem, const void* gmem) {
    asm volatile("cp.async.cg.shared.global [%0], [%1], 16;" :: "r"(smem), "l"(gmem));
}
#define CP_COMMIT() asm volatile("cp.async.commit_group;")
#define CP_WAIT0()  asm volatile("cp.async.wait_group 0;")
#define CP_WAIT1()  asm volatile("cp.async.wait_group 1;")

// ---------------- mma.sync m16n8k16 f16 (fp32 accum) ----------------
__device__ __forceinline__ void mma_f16(float* d, const uint32_t* a, const uint32_t* b) {
    asm volatile(
        "mma.sync.aligned.m16n8k16.row.col.f32.f16.f16.f32 "
        "{%0,%1,%2,%3}, {%4,%5,%6,%7}, {%8,%9}, {%0,%1,%2,%3};\n"
        : "+f"(d[0]), "+f"(d[1]), "+f"(d[2]), "+f"(d[3])
        : "r"(a[0]), "r"(a[1]), "r"(a[2]), "r"(a[3]), "r"(b[0]), "r"(b[1]));
}

// ================= ONE-SHOT K=256 GEMM body (128x64 tile) =====================
#define LDL 264
#define SM256_BYTES ((128 + 64) * LDL * 2)   // 101376 B

__device__ __forceinline__ void
hgemm256_body(const __half* __restrict__ A, const __half* __restrict__ WT,
              const float* __restrict__ bias, const float* __restrict__ resid,
              float* __restrict__ C, __half* __restrict__ Ch, int N,
              int row0, int col0, __half* hsm) {
    __half* Bsmem = hsm + 128 * LDL;
    const int t = threadIdx.x;
    const int lane = t & 31;
    const int wid  = t >> 5;
    const int wm = (wid & 3) * 32;
    const int wn = (wid >> 2) * 32;
    const int g   = lane >> 2;
    const int tig = lane & 3;

    const uint32_t as_u = (uint32_t)__cvta_generic_to_shared(hsm);
    const uint32_t bs_u = (uint32_t)__cvta_generic_to_shared(Bsmem);

    #pragma unroll
    for (int j = 0; j < 16; j++) {
        int slot = t + 256 * j;
        int r = slot >> 5, seg = slot & 31;
        cp_async16(as_u + (uint32_t)((r * LDL + seg * 8) * 2),
                   A + (size_t)(row0 + r) * 256 + seg * 8);
    }
    #pragma unroll
    for (int j = 0; j < 8; j++) {
        int slot = t + 256 * j;
        int r = slot >> 5, seg = slot & 31;
        cp_async16(bs_u + (uint32_t)((r * LDL + seg * 8) * 2),
                   WT + (size_t)(col0 + r) * 256 + seg * 8);
    }
    CP_COMMIT();

    float acc[2][4][4];
    #pragma unroll
    for (int i = 0; i < 2; i++)
        #pragma unroll
        for (int j = 0; j < 4; j++)
            #pragma unroll
            for (int r = 0; r < 4; r++) acc[i][j][r] = 0.f;

    CP_WAIT0();
    __syncthreads();

    #pragma unroll
    for (int ks = 0; ks < 16; ks++) {
        const int k0h = ks * 16;
        uint32_t bfr[4][2];
        #pragma unroll
        for (int nt = 0; nt < 4; nt++) {
            const __half* p = Bsmem + (wn + nt * 8 + g) * LDL + k0h + 2 * tig;
            bfr[nt][0] = *(const uint32_t*)(p);
            bfr[nt][1] = *(const uint32_t*)(p + 8);
        }
        #pragma unroll
        for (int mt = 0; mt < 2; mt++) {
            const __half* p = hsm + (wm + mt * 16 + g) * LDL + k0h + 2 * tig;
            uint32_t afr[4];
            afr[0] = *(const uint32_t*)(p);
            afr[1] = *(const uint32_t*)(p + 8 * LDL);
            afr[2] = *(const uint32_t*)(p + 8);
            afr[3] = *(const uint32_t*)(p + 8 * LDL + 8);
            #pragma unroll
            for (int nt = 0; nt < 4; nt++) mma_f16(acc[mt][nt], afr, bfr[nt]);
        }
    }

    #pragma unroll
    for (int mt = 0; mt < 2; mt++) {
        int r0 = row0 + wm + mt * 16 + g;
        #pragma unroll
        for (int nt = 0; nt < 4; nt++) {
            int cc = col0 + wn + nt * 8 + tig * 2;
            float2 bv = *(const float2*)(bias + cc);
            float2 v0, v1;
            v0.x = acc[mt][nt][0] + bv.x;
            v0.y = acc[mt][nt][1] + bv.y;
            v1.x = acc[mt][nt][2] + bv.x;
            v1.y = acc[mt][nt][3] + bv.y;
            if (resid) {
                float2 ra = *(const float2*)(resid + (size_t)r0 * N + cc);
                float2 rb = *(const float2*)(resid + (size_t)(r0 + 8) * N + cc);
                v0.x += ra.x; v0.y += ra.y;
                v1.x += rb.x; v1.y += rb.y;
            }
            if (C) {
                *(float2*)(C + (size_t)r0 * N + cc)       = v0;
                *(float2*)(C + (size_t)(r0 + 8) * N + cc) = v1;
            }
            if (Ch) {
                *(__half2*)(Ch + (size_t)r0 * N + cc)       = __floats2half2_rn(v0.x, v0.y);
                *(__half2*)(Ch + (size_t)(r0 + 8) * N + cc) = __floats2half2_rn(v1.x, v1.y);
            }
        }
    }
}

__global__ void __launch_bounds__(256)
hgemm256_kernel(const __half* __restrict__ A, const __half* __restrict__ WT,
                const float* __restrict__ bias, const float* __restrict__ resid,
                float* __restrict__ C, __half* __restrict__ Ch, int N) {
    extern __shared__ __half hsm[];
    hgemm256_body(A, WT, bias, resid, C, Ch, N, blockIdx.y * 128, blockIdx.x * 64, hsm);
}

// dual launch: bx<4 -> val GEMM (half out), bx>=4 -> offaw GEMM (fp32 out)
__global__ void __launch_bounds__(256)
hgemm256_dual_kernel(const __half* __restrict__ Aval, const __half* __restrict__ WTval,
                     const float* __restrict__ bval, __half* __restrict__ Cvalh,
                     const __half* __restrict__ Aoff, const __half* __restrict__ WToff,
                     const float* __restrict__ boff, float* __restrict__ Coff) {
    extern __shared__ __half hsm[];
    int bx = blockIdx.x;
    if (bx < 4) {
        hgemm256_body(Aval, WTval, bval, nullptr, nullptr, Cvalh, 256,
                      blockIdx.y * 128, bx * 64, hsm);
    } else {
        hgemm256_body(Aoff, WToff, boff, nullptr, Coff, nullptr, 384,
                      blockIdx.y * 128, (bx - 4) * 64, hsm);
    }
}

// ================= chunked 3-stage GEMM (for K=1024 fc2) =======================
#define LDH 40
#define STG 3
#define STAGE_A (128 * LDH)
#define STAGE_B (64 * LDH)

__global__ void __launch_bounds__(256)
hgemm_kernel(const __half* __restrict__ A, const __half* __restrict__ WT,
             const float* __restrict__ bias, const float* __restrict__ resid,
             float* __restrict__ C, __half* __restrict__ Ch, int N, int K) {
    extern __shared__ __half hsm[];
    __half* Bsmem = hsm + STG * STAGE_A;

    const int t = threadIdx.x;
    const int lane = t & 31;
    const int wid  = t >> 5;
    const int wm = (wid & 3) * 32;
    const int wn = (wid >> 2) * 32;
    const int g   = lane >> 2;
    const int tig = lane & 3;
    const int row0 = blockIdx.y * 128;
    const int col0 = blockIdx.x * 64;

    const uint32_t as_u = (uint32_t)__cvta_generic_to_shared(hsm);
    const uint32_t bs_u = (uint32_t)__cvta_generic_to_shared(Bsmem);

    float acc[2][4][4];
    #pragma unroll
    for (int i = 0; i < 2; i++)
        #pragma unroll
        for (int j = 0; j < 4; j++)
            #pragma unroll
            for (int r = 0; r < 4; r++) acc[i][j][r] = 0.f;

    const int NC = K >> 5;

    #pragma unroll
    for (int pc = 0; pc < 2; pc++) {
        const int k0 = pc << 5;
        const int soA = pc * STAGE_A;
        #pragma unroll
        for (int j = 0; j < 2; j++) {
            int slot = t + 256 * j;
            int r = slot >> 2, seg = slot & 3;
            cp_async16(as_u + (uint32_t)((soA + r * LDH + seg * 8) * 2),
                       A + (size_t)(row0 + r) * K + k0 + seg * 8);
        }
        const int soB = pc * STAGE_B;
        int r = t >> 2, seg = t & 3;
        cp_async16(bs_u + (uint32_t)((soB + r * LDH + seg * 8) * 2),
                   WT + (size_t)(col0 + r) * K + k0 + seg * 8);
        CP_COMMIT();
    }

    int stage = 0, pstage = 2;
    for (int c = 0; c < NC; c++) {
        if (c == NC - 1) { CP_WAIT0(); } else { CP_WAIT1(); }
        __syncthreads();
        if (c + 2 < NC) {
            const int k0 = (c + 2) << 5;
            const int soA = pstage * STAGE_A;
            #pragma unroll
            for (int j = 0; j < 2; j++) {
                int slot = t + 256 * j;
                int r = slot >> 2, seg = slot & 3;
                cp_async16(as_u + (uint32_t)((soA + r * LDH + seg * 8) * 2),
                           A + (size_t)(row0 + r) * K + k0 + seg * 8);
            }
            const int soB = pstage * STAGE_B;
            int r = t >> 2, seg = t & 3;
            cp_async16(bs_u + (uint32_t)((soB + r * LDH + seg * 8) * 2),
                       WT + (size_t)(col0 + r) * K + k0 + seg * 8);
            CP_COMMIT();
        }
        const __half* Asb = hsm   + stage * STAGE_A;
        const __half* Bsb = Bsmem + stage * STAGE_B;
        #pragma unroll
        for (int ks = 0; ks < 2; ks++) {
            const int k0h = ks * 16;
            uint32_t bfr[4][2];
            #pragma unroll
            for (int nt = 0; nt < 4; nt++) {
                const __half* p = Bsb + (wn + nt * 8 + g) * LDH + k0h + 2 * tig;
                bfr[nt][0] = *(const uint32_t*)(p);
                bfr[nt][1] = *(const uint32_t*)(p + 8);
            }
            #pragma unroll
            for (int mt = 0; mt < 2; mt++) {
                const __half* p = Asb + (wm + mt * 16 + g) * LDH + k0h + 2 * tig;
                uint32_t afr[4];
                afr[0] = *(const uint32_t*)(p);
                afr[1] = *(const uint32_t*)(p + 8 * LDH);
                afr[2] = *(const uint32_t*)(p + 8);
                afr[3] = *(const uint32_t*)(p + 8 * LDH + 8);
                #pragma unroll
                for (int nt = 0; nt < 4; nt++) mma_f16(acc[mt][nt], afr, bfr[nt]);
            }
        }
        stage = (stage == STG - 1) ? 0 : stage + 1;
        pstage = (pstage == STG - 1) ? 0 : pstage + 1;
    }
    __syncthreads();

    #pragma unroll
    for (int mt = 0; mt < 2; mt++) {
        int r0 = row0 + wm + mt * 16 + g;
        #pragma unroll
        for (int nt = 0; nt < 4; nt++) {
            int cc = col0 + wn + nt * 8 + tig * 2;
            float2 bv = *(const float2*)(bias + cc);
            float2 v0, v1;
            v0.x = acc[mt][nt][0] + bv.x;
            v0.y = acc[mt][nt][1] + bv.y;
            v1.x = acc[mt][nt][2] + bv.x;
            v1.y = acc[mt][nt][3] + bv.y;
            if (resid) {
                float2 ra = *(const float2*)(resid + (size_t)r0 * N + cc);
                float2 rb = *(const float2*)(resid + (size_t)(r0 + 8) * N + cc);
                v0.x += ra.x; v0.y += ra.y;
                v1.x += rb.x; v1.y += rb.y;
            }
            if (C) {
                *(float2*)(C + (size_t)r0 * N + cc)       = v0;
                *(float2*)(C + (size_t)(r0 + 8) * N + cc) = v1;
            }
            if (Ch) {
                *(__half2*)(Ch + (size_t)r0 * N + cc)       = __floats2half2_rn(v0.x, v0.y);
                *(__half2*)(Ch + (size_t)(r0 + 8) * N + cc) = __floats2half2_rn(v1.x, v1.y);
            }
        }
    }
}

#define GEMM_SMEM_BYTES ((unsigned)(STG * (STAGE_A + STAGE_B) * 2))   // 46080 B

// ======= merged prologue: weight transposes + bias concat + q/v flatten =======
__global__ void __launch_bounds__(256)
prologue_kernel(const float* __restrict__ s_val, const float* __restrict__ s_off,
                const float* __restrict__ s_attn, const float* __restrict__ s_out,
                const float* __restrict__ s_fc1, const float* __restrict__ s_fc2,
                const float* __restrict__ b_off, const float* __restrict__ b_attn,
                __half* __restrict__ d_val, __half* __restrict__ d_offaw,
                __half* __restrict__ d_out, __half* __restrict__ d_fc1,
                __half* __restrict__ d_fc2, float* __restrict__ d_b_offaw,
                const float* __restrict__ q0, const float* __restrict__ v0,
                const float* __restrict__ q1, const float* __restrict__ v1,
                const float* __restrict__ q2, const float* __restrict__ v2,
                const float* __restrict__ q3, const float* __restrict__ v3,
                __half* __restrict__ gqh, float* __restrict__ gq32,
                float* __restrict__ gv) {
    __shared__ float pool[2 * 32 * 33];
    int blk = blockIdx.x;
    int t = threadIdx.x;
    if (blk < 737) {
        int u = blk;
        if (u == 736) {
            if (t < 128) {
                d_b_offaw[t]       = b_off[t];
                d_b_offaw[t + 128] = b_off[t + 128];
            } else {
                int j = t - 128;
                d_b_offaw[256 + j] = b_attn[j];
            }
            return;
        }
        const float* src; __half* dst; int K, N;
        if      (u < 64)  {            src = s_val;  dst = d_val;             K = 256;  N = 256; }
        else if (u < 128) { u -= 64;   src = s_off;  dst = d_offaw;           K = 256;  N = 256; }
        else if (u < 160) { u -= 128;  src = s_attn; dst = d_offaw + 256*256; K = 256;  N = 128; }
        else if (u < 224) { u -= 160;  src = s_out;  dst = d_out;             K = 256;  N = 256; }
        else if (u < 480) { u -= 224;  src = s_fc1;  dst = d_fc1;             K = 256;  N = 1024; }
        else              { u -= 480;  src = s_fc2;  dst = d_fc2;             K = 1024; N = 256; }
        int nt = N >> 5;
        int by = (u / nt) * 32, bx = (u % nt) * 32;
        float (*tile)[33] = (float(*)[33])pool;
        int tx = t & 31, ty = t >> 5;
        #pragma unroll
        for (int i = 0; i < 32; i += 8)
            tile[ty + i][tx] = src[(size_t)(by + ty + i) * N + bx + tx];
        __syncthreads();
        #pragma unroll
        for (int i = 0; i < 32; i += 8)
            dst[(size_t)(bx + ty + i) * K + by + tx] = __float2half_rn(tile[tx][ty + i]);
    } else {
        int fb = blk - 737;
        int b = fb / 1360;
        int u = fb % 1360;
        const float *qs, *vs; int n, start;
        if      (u < 1024) {            qs = q0; vs = v0; n = 4096; start = 0; }
        else if (u < 1280) { u -= 1024; qs = q1; vs = v1; n = 1024; start = 4096; }
        else if (u < 1344) { u -= 1280; qs = q2; vs = v2; n = 256;  start = 5120; }
        else               { u -= 1344; qs = q3; vs = v3; n = 64;   start = 5376; }
        int pt = n >> 5;
        int ct = u / pt;
        int pi = u % pt;
        float (*tq)[33] = (float(*)[33])pool;
        float (*tv)[33] = (float(*)[33])(pool + 32 * 33);
        int tx = t & 31, ty = t >> 5;
        const float* qb = qs + (size_t)(b * DIM + ct * 32) * n + pi * 32;
        const float* vb = vs + (size_t)(b * DIM + ct * 32) * n + pi * 32;
        #pragma unroll
        for (int i = 0; i < 32; i += 8) {
            tq[ty + i][tx] = qb[(size_t)(ty + i) * n + tx];
            tv[ty + i][tx] = vb[(size_t)(ty + i) * n + tx];
        }
        __syncthreads();
        size_t obase = ((size_t)b * NQ + start + pi * 32) * DIM + ct * 32;
        #pragma unroll
        for (int i = 0; i < 32; i += 8) {
            float qv = tq[tx][ty + i];
            gq32[obase + (size_t)(ty + i) * DIM + tx] = qv;
            gqh [obase + (size_t)(ty + i) * DIM + tx] = __float2half_rn(qv);
            gv  [obase + (size_t)(ty + i) * DIM + tx] = tv[tx][ty + i];
        }
    }
}

// ---------------- layernorm (fp32 in, half out) ----------------
__global__ void layernorm_kernel(const float* __restrict__ x, const float* __restrict__ g,
                                 const float* __restrict__ bia, __half* __restrict__ out) {
    int row = blockIdx.x;
    int t = threadIdx.x;
    float v = x[(size_t)row * DIM + t];
    __shared__ float sm[40];
    float s = v;
    #pragma unroll
    for (int o = 16; o > 0; o >>= 1) s += __shfl_xor_sync(0xffffffffu, s, o);
    if ((t & 31) == 0) sm[t >> 5] = s;
    __syncthreads();
    if (t < 8) {
        float z = sm[t];
        #pragma unroll
        for (int o = 4; o > 0; o >>= 1) z += __shfl_xor_sync(0xffu, z, o);
        if (t == 0) sm[32] = z;
    }
    __syncthreads();
    float mean = sm[32] * (1.0f / DIM);
    float d = v - mean;
    float s2 = d * d;
    #pragma unroll
    for (int o = 16; o > 0; o >>= 1) s2 += __shfl_xor_sync(0xffffffffu, s2, o);
    if ((t & 31) == 0) sm[8 + (t >> 5)] = s2;
    __syncthreads();
    if (t < 8) {
        float z = sm[8 + t];
        #pragma unroll
        for (int o = 4; o > 0; o >>= 1) z += __shfl_xor_sync(0xffu, z, o);
        if (t == 0) sm[33] = z;
    }
    __syncthreads();
    float var = sm[33] * (1.0f / DIM);
    out[(size_t)row * DIM + t] = __float2half_rn(d * rsqrtf(var + 1e-5f) * g[t] + bia[t]);
}

// ---------------- deformable sampling v4: 16B gathers + half2 math ------------
// warp = (b, q, head). lane = ph(2b) | cp(1b) | c8(2b):
//   ph = point 0..3 within level, cp = corner-pair (y-row), c8 = 16B channel group.
__device__ __forceinline__ __half2 h2shfl_down(__half2 v, int d) {
    uint32_t u = *reinterpret_cast<uint32_t*>(&v);
    u = __shfl_down_sync(0xffffffffu, u, d);
    return *reinterpret_cast<__half2*>(&u);
}

__global__ void __launch_bounds__(256)
deform_kernel(const __half* __restrict__ val, const float* __restrict__ offaw,
              __half* __restrict__ samp) {
    const unsigned FULL = 0xffffffffu;
    int gw = (blockIdx.x * blockDim.x + threadIdx.x) >> 5;
    int lane = threadIdx.x & 31;
    if (gw >= MROWS * NH) return;
    int hh = gw % NH;
    int q  = (gw / NH) % NQ;
    int b  = gw / (NH * NQ);
    int ph = lane >> 3;          // point 0..3
    int cp = (lane >> 2) & 1;    // corner pair (y row)
    int c8 = lane & 3;           // 8-half channel group (16B)

    int lqv, local;
    if (q < 4096)      { lqv = 0; local = q; }
    else if (q < 5120) { lqv = 1; local = q - 4096; }
    else if (q < 5376) { lqv = 2; local = q - 5120; }
    else               { lqv = 3; local = q - 5376; }
    int szq = LVL_SIZE[lqv];
    float refx = ((local % szq) + 0.5f) / szq;
    float refy = ((local / szq) + 0.5f) / szq;

    const float* rowp = offaw + (size_t)(b * NQ + q) * 384;
    float offv  = rowp[hh * 32 + lane];
    float awraw = rowp[256 + hh * 16 + (lane & 15)];

    // softmax over 16 (per 16-lane group; both groups identical)
    float mx = awraw;
    #pragma unroll
    for (int o = 8; o > 0; o >>= 1) mx = fmaxf(mx, __shfl_xor_sync(FULL, mx, o, 16));
    float e = __expf(awraw - mx);
    float ssum = e;
    #pragma unroll
    for (int o = 8; o > 0; o >>= 1) ssum += __shfl_xor_sync(FULL, ssum, o, 16);
    float myaw = e / ssum;

    __half2 hz = __floats2half2_rn(0.f, 0.f);
    __half2 hacc0 = hz, hacc1 = hz, hacc2 = hz, hacc3 = hz;

    #pragma unroll
    for (int l = 0; l < NL; l++) {
        int w = LVL_SIZE[l];
        int startl = LVL_START[l];
        const __half* vbase = val + ((size_t)b * NQ + startl) * DIM + hh * HD + 8 * c8;
        float inv = 1.0f / (float)w;
        int j = l * NP + ph;
        float ox = __shfl_sync(FULL, offv, 2 * j);
        float oy = __shfl_sync(FULL, offv, 2 * j + 1);
        float a  = __shfl_sync(FULL, myaw, j);
        float sx = (refx + ox * inv) * w - 0.5f;
        float sy = (refy + oy * inv) * w - 0.5f;
        int x0 = (int)floorf(sx);
        int y0 = (int)floorf(sy);
        float lx = sx - (float)x0;
        float ly = sy - (float)y0;

        int yi = y0 + cp;
        float awy = a * (cp ? ly : 1.f - ly);
        bool yok = (yi >= 0) & (yi < w);
        int cy = min(max(yi, 0), w - 1);
        #pragma unroll
        for (int cc = 0; cc < 2; cc++) {
            int xi = x0 + cc;
            float wx = cc ? lx : 1.f - lx;
            float m = (yok && xi >= 0 && xi < w) ? awy * wx : 0.f;
            int cx = min(max(xi, 0), w - 1);
            uint4 hv = *(const uint4*)(vbase + (size_t)(cy * w + cx) * DIM);
            __half2 mh = __float2half2_rn(m);
            hacc0 = __hfma2(mh, *reinterpret_cast<__half2*>(&hv.x), hacc0);
            hacc1 = __hfma2(mh, *reinterpret_cast<__half2*>(&hv.y), hacc1);
            hacc2 = __hfma2(mh, *reinterpret_cast<__half2*>(&hv.z), hacc2);
            hacc3 = __hfma2(mh, *reinterpret_cast<__half2*>(&hv.w), hacc3);
        }
    }
    // reduce across cp (offset 4) and ph (offsets 8, 16)
    #pragma unroll
    for (int d = 16; d >= 4; d >>= 1) {
        hacc0 = __hadd2(hacc0, h2shfl_down(hacc0, d));
        hacc1 = __hadd2(hacc1, h2shfl_down(hacc1, d));
        hacc2 = __hadd2(hacc2, h2shfl_down(hacc2, d));
        hacc3 = __hadd2(hacc3, h2shfl_down(hacc3, d));
    }
    if (lane < 4) {
        uint4 u;
        u.x = *reinterpret_cast<uint32_t*>(&hacc0);
        u.y = *reinterpret_cast<uint32_t*>(&hacc1);
        u.z = *reinterpret_cast<uint32_t*>(&hacc2);
        u.w = *reinterpret_cast<uint32_t*>(&hacc3);
        *(uint4*)(samp + (size_t)(b * NQ + q) * DIM + hh * HD + 8 * lane) = u;
    }
}

// ---------------- depthwise 3x3 + bias + GELU, half2-vectorized ---------------
__global__ void __launch_bounds__(256)
dwconv_gelu_tiled(const __half* __restrict__ h1, const float* __restrict__ Wdw,
                  const float* __restrict__ bdw, __half* __restrict__ h2) {
    extern __shared__ float2 ts2[];   // [100][64]
    int tile = blockIdx.x;
    int c0 = blockIdx.y * 128;
    int b = blockIdx.z;
    int l, tx, ty;
    if      (tile < 64) { l = 0; ty = tile >> 3; tx = tile & 7; }
    else if (tile < 80) { int u = tile - 64; l = 1; ty = u >> 2; tx = u & 3; }
    else if (tile < 84) { int u = tile - 80; l = 2; ty = u >> 1; tx = u & 1; }
    else                { l = 3; ty = 0; tx = 0; }
    int w = LVL_SIZE[l];
    int start = LVL_START[l];
    int t = threadIdx.x;
    int c2 = t & 63;
    int grp = t >> 6;

    const __half* hbase = h1 + ((size_t)b * NQ + start) * HID + c0 + 2 * c2;
    for (int p = grp; p < 100; p += 4) {
        int py = p / 10 - 1 + ty * 8;
        int px = p % 10 - 1 + tx * 8;
        float2 v = make_float2(0.f, 0.f);
        if (py >= 0 && py < w && px >= 0 && px < w)
            v = __half22float2(*(const __half2*)(hbase + (size_t)(py * w + px) * HID));
        ts2[p * 64 + c2] = v;
    }
    float2 w9[9];
    #pragma unroll
    for (int j = 0; j < 9; j++) w9[j] = *(const float2*)(Wdw + j * HID + c0 + 2 * c2);
    float2 bs = *(const float2*)(bdw + c0 + 2 * c2);
    __syncthreads();

    __half* obase = h2 + ((size_t)b * NQ + start + (ty * 8) * w + tx * 8) * HID + c0 + 2 * c2;
    for (int p = grp; p < 64; p += 4) {
        int py = p >> 3, px = p & 7;
        float ax = bs.x, ay = bs.y;
        #pragma unroll
        for (int ky = 0; ky < 3; ky++)
            #pragma unroll
            for (int kx = 0; kx < 3; kx++) {
                float2 v = ts2[((py + ky) * 10 + px + kx) * 64 + c2];
                float2 ww = w9[ky * 3 + kx];
                ax = fmaf(v.x, ww.x, ax);
                ay = fmaf(v.y, ww.y, ay);
            }
        float gx = ax * 0.5f * (1.0f + erff(ax * 0.70710678118654752440f));
        float gy = ay * 0.5f * (1.0f + erff(ay * 0.70710678118654752440f));
        *(__half2*)(obase + (size_t)(py * w + px) * HID) = __floats2half2_rn(gx, gy);
    }
}
#define DW_SMEM_BYTES (100u * 64u * 8u)   // 51200

// ---------------- launch ----------------
extern "C" void kernel_launch(void* const* d_in, const int* in_sizes, int n_in,
                              void* d_out, int out_size) {
    const float* q0 = (const float*)d_in[0];
    const float* v0 = (const float*)d_in[1];
    const float* q1 = (const float*)d_in[2];
    const float* v1 = (const float*)d_in[3];
    const float* q2 = (const float*)d_in[4];
    const float* v2 = (const float*)d_in[5];
    const float* q3 = (const float*)d_in[6];
    const float* v3 = (const float*)d_in[7];
    const float* vn_g  = (const float*)d_in[8];
    const float* vn_b  = (const float*)d_in[9];
    const float* W_off = (const float*)d_in[10];
    const float* b_off = (const float*)d_in[11];
    const float* W_attn= (const float*)d_in[12];
    const float* b_attn= (const float*)d_in[13];
    const float* W_val = (const float*)d_in[14];
    const float* b_val = (const float*)d_in[15];
    const float* W_out = (const float*)d_in[16];
    const float* b_out = (const float*)d_in[17];
    const float* W_fc1 = (const float*)d_in[18];
    const float* b_fc1 = (const float*)d_in[19];
    const float* W_dw  = (const float*)d_in[20];
    const float* b_dw  = (const float*)d_in[21];
    const float* W_fc2 = (const float*)d_in[22];
    const float* b_fc2 = (const float*)d_in[23];
    float* out = (float*)d_out;

    __half *gqh, *gvnh, *gvalh, *gsamph, *gxh, *gh1h, *gh2h;
    __half *wtval, *wtoffaw, *wtout, *wtfc1, *wtfc2;
    float *gq32, *gv, *goffaw, *gx, *boffaw;
    cudaGetSymbolAddress((void**)&gqh,    g_qh);
    cudaGetSymbolAddress((void**)&gq32,   g_q32);
    cudaGetSymbolAddress((void**)&gv,     g_value);
    cudaGetSymbolAddress((void**)&gvnh,   g_vnh);
    cudaGetSymbolAddress((void**)&gvalh,  g_valh);
    cudaGetSymbolAddress((void**)&goffaw, g_offaw);
    cudaGetSymbolAddress((void**)&gsamph, g_samph);
    cudaGetSymbolAddress((void**)&gx,     g_x);
    cudaGetSymbolAddress((void**)&gxh,    g_xh);
    cudaGetSymbolAddress((void**)&gh1h,   g_h1h);
    cudaGetSymbolAddress((void**)&gh2h,   g_h2h);
    cudaGetSymbolAddress((void**)&wtval,  g_WT_val);
    cudaGetSymbolAddress((void**)&wtoffaw,g_WT_offaw);
    cudaGetSymbolAddress((void**)&boffaw, g_b_offaw);
    cudaGetSymbolAddress((void**)&wtout,  g_WT_out);
    cudaGetSymbolAddress((void**)&wtfc1,  g_WT_fc1);
    cudaGetSymbolAddress((void**)&wtfc2,  g_WT_fc2);

    cudaFuncSetAttribute(hgemm256_kernel,
                         cudaFuncAttributeMaxDynamicSharedMemorySize, SM256_BYTES);
    cudaFuncSetAttribute(hgemm256_dual_kernel,
                         cudaFuncAttributeMaxDynamicSharedMemorySize, SM256_BYTES);
    cudaFuncSetAttribute(hgemm_kernel,
                         cudaFuncAttributeMaxDynamicSharedMemorySize, GEMM_SMEM_BYTES);
    cudaFuncSetAttribute(dwconv_gelu_tiled,
                         cudaFuncAttributeMaxDynamicSharedMemorySize, DW_SMEM_BYTES);

    prologue_kernel<<<737 + 2720, 256>>>(W_val, W_off, W_attn, W_out, W_fc1, W_fc2,
                                         b_off, b_attn,
                                         wtval, wtoffaw, wtout, wtfc1, wtfc2, boffaw,
                                         q0, v0, q1, v1, q2, v2, q3, v3,
                                         gqh, gq32, gv);

    layernorm_kernel<<<MROWS, 256>>>(gv, vn_g, vn_b, gvnh);

    const int MT = MROWS / 128;  // 85
    hgemm256_dual_kernel<<<dim3(10, MT), 256, SM256_BYTES>>>(gvnh, wtval, b_val, gvalh,
                                                             gqh, wtoffaw, boffaw, goffaw);

    deform_kernel<<<(MROWS * NH * 32 + 255) / 256, 256>>>(gvalh, goffaw, gsamph);

    hgemm256_kernel<<<dim3(DIM / 64, MT), 256, SM256_BYTES>>>(gsamph, wtout, b_out, gq32,
                                                              gx, gxh, DIM);
    hgemm256_kernel<<<dim3(HID / 64, MT), 256, SM256_BYTES>>>(gxh, wtfc1, b_fc1, nullptr,
                                                              nullptr, gh1h, HID);

    dwconv_gelu_tiled<<<dim3(85, 8, BB), 256, DW_SMEM_BYTES>>>(gh1h, W_dw, b_dw, gh2h);

    hgemm_kernel<<<dim3(DIM / 64, MT), 256, GEMM_SMEM_BYTES>>>(gh2h, wtfc2, b_fc2, gx,
                                                               out, nullptr, DIM, HID);
}